// round 1
// baseline (speedup 1.0000x reference)
#include <cuda_runtime.h>
#include <math.h>

#define NOBS 72000
#define NBUK 9000
#define LMAXX 8
#define DIM 256
#define NTOK 8
#define DH 32
#define DEPTH 8
#define FFND 1024
#define OUTD 2048
#define CLAT 512

// ---------------- scratch (device globals: no allocation allowed) ----------
static __device__ float g_h  [NOBS * DIM];
static __device__ float g_ctx[NOBS * DIM];
static __device__ float g_q  [NOBS * DIM];
static __device__ float g_k  [NOBS * DIM];
static __device__ float g_v  [NOBS * DIM];
static __device__ float g_o  [NOBS * DIM];
static __device__ float g_trx[NOBS * DIM];
static __device__ float g_ln [NOBS * DIM];
static __device__ float g_ffn[NOBS * FFND];
static __device__ int   g_cnt[NBUK];
static __device__ int   g_row[NOBS];

__device__ __forceinline__ float gelu_tanh(float x) {
    // jax.nn.gelu(approximate=True): 0.5*x*(1+tanh(sqrt(2/pi)*(x+0.044715*x^3)))
    float x3 = x * x * x;
    float t = tanhf(0.7978845608028654f * (x + 0.044715f * x3));
    return 0.5f * x * (1.0f + t);
}

// ---------------- generic fp32 GEMM: C = act(A@B + bias) [+ res] [gated] ----
// A: [M,K] row-major, B: [K,N] row-major. N % 64 == 0, K % 16 == 0. M guarded.
__global__ __launch_bounds__(256, 3)
void k_gemm(const float* __restrict__ A, const float* __restrict__ B,
            const float* __restrict__ bias, const float* __restrict__ res,
            const int* __restrict__ gate, float* __restrict__ C,
            int M, int N, int K, int act)
{
    __shared__ __align__(16) float As[16][128];
    __shared__ __align__(16) float Bs[16][64];

    const int tid = threadIdx.x;
    const int tx = tid & 15;        // 16 col-threads
    const int ty = tid >> 4;        // 16 row-threads
    const int rowBase = blockIdx.y << 7;   // BM = 128
    const int colBase = blockIdx.x << 6;   // BN = 64

    float acc[8][4];
#pragma unroll
    for (int i = 0; i < 8; i++)
#pragma unroll
        for (int j = 0; j < 4; j++) acc[i][j] = 0.0f;

    for (int kt = 0; kt < K; kt += 16) {
        // load A tile 128x16 (transposed into As[k][m])
#pragma unroll
        for (int r = 0; r < 2; r++) {
            int fid = tid + (r << 8);       // 0..511 float4 ids
            int m   = fid >> 2;             // 0..127
            int kq  = (fid & 3) << 2;       // 0,4,8,12
            int gm  = rowBase + m;
            float4 a = (gm < M) ? *(const float4*)(A + (size_t)gm * K + kt + kq)
                                : make_float4(0.f, 0.f, 0.f, 0.f);
            As[kq + 0][m] = a.x; As[kq + 1][m] = a.y;
            As[kq + 2][m] = a.z; As[kq + 3][m] = a.w;
        }
        // load B tile 16x64
        {
            int kk = tid >> 4;
            int n4 = (tid & 15) << 2;
            *(float4*)(&Bs[kk][n4]) =
                *(const float4*)(B + (size_t)(kt + kk) * N + colBase + n4);
        }
        __syncthreads();

#pragma unroll
        for (int kk = 0; kk < 16; kk++) {
            float4 a0 = *(const float4*)(&As[kk][ty << 3]);
            float4 a1 = *(const float4*)(&As[kk][(ty << 3) + 4]);
            float4 b0 = *(const float4*)(&Bs[kk][tx << 2]);
            float ra[8] = {a0.x, a0.y, a0.z, a0.w, a1.x, a1.y, a1.z, a1.w};
            float rb[4] = {b0.x, b0.y, b0.z, b0.w};
#pragma unroll
            for (int i = 0; i < 8; i++)
#pragma unroll
                for (int j = 0; j < 4; j++)
                    acc[i][j] = fmaf(ra[i], rb[j], acc[i][j]);
        }
        __syncthreads();
    }

    const int gn = colBase + (tx << 2);
    float4 bsv = bias ? *(const float4*)(bias + gn) : make_float4(0.f, 0.f, 0.f, 0.f);
#pragma unroll
    for (int i = 0; i < 8; i++) {
        int gm = rowBase + (ty << 3) + i;
        if (gm >= M) break;
        float4 c;
        c.x = acc[i][0] + bsv.x; c.y = acc[i][1] + bsv.y;
        c.z = acc[i][2] + bsv.z; c.w = acc[i][3] + bsv.w;
        if (act) {
            c.x = gelu_tanh(c.x); c.y = gelu_tanh(c.y);
            c.z = gelu_tanh(c.z); c.w = gelu_tanh(c.w);
        }
        if (res) {
            float4 rv = *(const float4*)(res + (size_t)gm * N + gn);
            c.x += rv.x; c.y += rv.y; c.z += rv.z; c.w += rv.w;
        }
        if (gate && gate[gm] == 0) { c.x = 0.f; c.y = 0.f; c.z = 0.f; c.w = 0.f; }
        *(float4*)(C + (size_t)gm * N + gn) = c;
    }
}

// ---------------- layernorm: one warp per 256-wide row ----------------------
__global__ void k_ln(const float* __restrict__ X, float* __restrict__ Y,
                     const float* __restrict__ G, const float* __restrict__ Bb)
{
    int row  = blockIdx.x * 8 + (threadIdx.x >> 5);
    int lane = threadIdx.x & 31;
    const float* x = X + (size_t)row * DIM;
    float v[8];
    float s = 0.f;
#pragma unroll
    for (int r = 0; r < 8; r++) { v[r] = x[lane + (r << 5)]; s += v[r]; }
#pragma unroll
    for (int off = 16; off; off >>= 1) s += __shfl_xor_sync(0xffffffffu, s, off);
    float mean = s * (1.0f / 256.0f);
    float vs = 0.f;
#pragma unroll
    for (int r = 0; r < 8; r++) { float d = v[r] - mean; vs = fmaf(d, d, vs); }
#pragma unroll
    for (int off = 16; off; off >>= 1) vs += __shfl_xor_sync(0xffffffffu, vs, off);
    float inv = rsqrtf(vs * (1.0f / 256.0f) + 1e-5f);
    float* y = Y + (size_t)row * DIM;
#pragma unroll
    for (int r = 0; r < 8; r++) {
        int c = lane + (r << 5);
        y[c] = (v[r] - mean) * inv * G[c] + Bb[c];
    }
}

// ---------------- per-bucket cross attention (NTOK=8 q, LMAX=8 kv) ----------
__global__ void k_attn(const float* __restrict__ Q, const float* __restrict__ Kx,
                       const float* __restrict__ V, float* __restrict__ O)
{
    __shared__ __align__(16) float sQ[NTOK * DIM];
    __shared__ __align__(16) float sK[LMAXX * DIM];
    __shared__ __align__(16) float sV[LMAXX * DIM];
    int b = blockIdx.x;
    int tid = threadIdx.x;  // 64 threads
    const float4* q4 = (const float4*)(Q + (size_t)b * NTOK * DIM);
    const float4* k4 = (const float4*)(Kx + (size_t)b * LMAXX * DIM);
    const float4* v4 = (const float4*)(V + (size_t)b * LMAXX * DIM);
#pragma unroll
    for (int r = 0; r < 8; r++) {
        ((float4*)sQ)[tid + r * 64] = q4[tid + r * 64];
        ((float4*)sK)[tid + r * 64] = k4[tid + r * 64];
        ((float4*)sV)[tid + r * 64] = v4[tid + r * 64];
    }
    int cnt = g_cnt[b];
    __syncthreads();

    int h = tid >> 3, qi = tid & 7;
    const float* qp = sQ + qi * DIM + h * DH;
    float qr[DH];
#pragma unroll
    for (int d = 0; d < DH; d++) qr[d] = qp[d];

    float sc[LMAXX];
    float mx = -1e30f;
#pragma unroll
    for (int j = 0; j < LMAXX; j++) {
        const float* kp = sK + j * DIM + h * DH;
        float s = 0.f;
#pragma unroll
        for (int d = 0; d < DH; d++) s = fmaf(qr[d], kp[d], s);
        s = s * 0.17677669529663689f;   // 1/sqrt(32)
        if (j >= cnt) s -= 1e9f;        // additive mask
        sc[j] = s;
        mx = fmaxf(mx, s);
    }
    float den = 0.f;
#pragma unroll
    for (int j = 0; j < LMAXX; j++) { sc[j] = expf(sc[j] - mx); den += sc[j]; }
    float inv = 1.0f / den;
    float o[DH];
#pragma unroll
    for (int d = 0; d < DH; d++) o[d] = 0.f;
#pragma unroll
    for (int j = 0; j < LMAXX; j++) {
        float a = sc[j] * inv;
        const float* vp = sV + j * DIM + h * DH;
#pragma unroll
        for (int d = 0; d < DH; d++) o[d] = fmaf(a, vp[d], o[d]);
    }
    float* op = O + (size_t)(b * NTOK + qi) * DIM + h * DH;
#pragma unroll
    for (int d = 0; d < DH; d++) op[d] = o[d];
}

// ---------------- dispatch helpers ------------------------------------------
__global__ void k_reset_cnt()
{
    int i = blockIdx.x * blockDim.x + threadIdx.x;
    if (i < NBUK) g_cnt[i] = 0;
}

__global__ void k_flatpos(const int* __restrict__ li)
{
    int i = blockIdx.x * blockDim.x + threadIdx.x;
    if (i >= NOBS) return;
    int d = li[3 * i], hh = li[3 * i + 1], w = li[3 * i + 2];
    int f = d * 1800 + hh * 60 + w;     // d*(H*W) + h*W + w
    int pos = atomicAdd(&g_cnt[f], 1);
    g_row[i] = (pos < LMAXX) ? (f * LMAXX + pos) : -1;
}

__global__ void k_scatter()
{
    int wid  = (blockIdx.x * blockDim.x + threadIdx.x) >> 5;
    int lane = threadIdx.x & 31;
    if (wid >= NOBS) return;
    int dst = g_row[wid];
    if (dst < 0) return;
    const float4* src = (const float4*)(g_h + (size_t)wid * DIM);
    float4* dp = (float4*)(g_ctx + (size_t)dst * DIM);
    dp[lane]      = src[lane];
    dp[lane + 32] = src[lane + 32];
}

__global__ void k_init_trx(const float* __restrict__ bg)
{
    int idx = blockIdx.x * blockDim.x + threadIdx.x;  // float4 index
    if (idx >= NOBS * DIM / 4) return;
    int row = idx >> 6;   // 64 float4 per row
    int t   = row & 7;
    int c4  = idx & 63;
    ((float4*)g_trx)[idx] = ((const float4*)bg)[t * 64 + c4];
}

// ---------------- launch ------------------------------------------------------
extern "C" void kernel_launch(void* const* d_in, const int* in_sizes, int n_in,
                              void* d_out, int out_size)
{
    const float* x     = (const float*)d_in[0];
    const int*   li    = (const int*)  d_in[1];
    const float* mlp_w = (const float*)d_in[2];
    const float* mlp_b = (const float*)d_in[3];
    const float* bg    = (const float*)d_in[4];
    const float* ln1g  = (const float*)d_in[5];
    const float* ln1b  = (const float*)d_in[6];
    const float* wq    = (const float*)d_in[7];
    const float* bq    = (const float*)d_in[8];
    const float* wk    = (const float*)d_in[9];
    const float* bk    = (const float*)d_in[10];
    const float* wv    = (const float*)d_in[11];
    const float* bv    = (const float*)d_in[12];
    const float* wo    = (const float*)d_in[13];
    const float* bo    = (const float*)d_in[14];
    const float* ln2g  = (const float*)d_in[15];
    const float* ln2b  = (const float*)d_in[16];
    const float* w1    = (const float*)d_in[17];
    const float* b1    = (const float*)d_in[18];
    const float* w2    = (const float*)d_in[19];
    const float* b2    = (const float*)d_in[20];
    const float* pw    = (const float*)d_in[21];
    const float* pb    = (const float*)d_in[22];
    float* out = (float*)d_out;
    (void)in_sizes; (void)n_in; (void)out_size;

    float *ph, *pctx, *pq, *pk, *pv, *po, *ptrx, *pln, *pffn;
    int *pcnt;
    cudaGetSymbolAddress((void**)&ph,   g_h);
    cudaGetSymbolAddress((void**)&pctx, g_ctx);
    cudaGetSymbolAddress((void**)&pq,   g_q);
    cudaGetSymbolAddress((void**)&pk,   g_k);
    cudaGetSymbolAddress((void**)&pv,   g_v);
    cudaGetSymbolAddress((void**)&po,   g_o);
    cudaGetSymbolAddress((void**)&ptrx, g_trx);
    cudaGetSymbolAddress((void**)&pln,  g_ln);
    cudaGetSymbolAddress((void**)&pffn, g_ffn);
    cudaGetSymbolAddress((void**)&pcnt, g_cnt);

    auto gemm = [](const float* A, const float* B, const float* bias,
                   const float* res, const int* gate, float* C,
                   int M, int N, int K, int act) {
        dim3 grid(N / 64, (M + 127) / 128);
        k_gemm<<<grid, 256>>>(A, B, bias, res, gate, C, M, N, K, act);
    };

    // --- obs feature MLP: fc1 -> gelu -> fc2 -> gelu -> fc3 ---
    gemm(x,   mlp_w,             mlp_b,       nullptr, nullptr, pln, NOBS, DIM, DIM, 1);
    gemm(pln, mlp_w + 65536,     mlp_b + 256, nullptr, nullptr, pq,  NOBS, DIM, DIM, 1);
    gemm(pq,  mlp_w + 2 * 65536, mlp_b + 512, nullptr, nullptr, ph,  NOBS, DIM, DIM, 0);

    // --- dispatch into [NB, LMAX, DIM] buckets ---
    k_reset_cnt<<<(NBUK + 255) / 256, 256>>>();
    k_flatpos<<<(NOBS + 255) / 256, 256>>>(li);
    k_scatter<<<NOBS / 8, 256>>>();
    k_init_trx<<<NOBS * DIM / 4 / 256, 256>>>(bg);

    // --- 8-layer cross-attention transformer ---
    for (int l = 0; l < DEPTH; l++) {
        k_ln<<<NBUK, 256>>>(ptrx, pln, ln1g + l * DIM, ln1b + l * DIM);
        gemm(pln,  wq + l * 65536, bq + l * DIM, nullptr, nullptr, pq, NOBS, DIM, DIM, 0);
        gemm(pctx, wk + l * 65536, bk + l * DIM, nullptr, nullptr, pk, NOBS, DIM, DIM, 0);
        gemm(pctx, wv + l * 65536, bv + l * DIM, nullptr, nullptr, pv, NOBS, DIM, DIM, 0);
        k_attn<<<NBUK, 64>>>(pq, pk, pv, po);
        gemm(po, wo + l * 65536, bo + l * DIM, ptrx, nullptr, ptrx, NOBS, DIM, DIM, 0);
        k_ln<<<NBUK, 256>>>(ptrx, pln, ln2g + l * DIM, ln2b + l * DIM);
        gemm(pln,  w1 + l * DIM * FFND, b1 + l * FFND, nullptr, nullptr, pffn, NOBS, FFND, DIM, 1);
        gemm(pffn, w2 + l * FFND * DIM, b2 + l * DIM,  ptrx,    nullptr, ptrx, NOBS, DIM, FFND, 0);
    }

    // --- final projection, gated by occupancy ---
    gemm(ptrx, pw, pb, nullptr, pcnt, out, NBUK, CLAT, OUTD, 0);
}

// round 2
// speedup vs baseline: 2.5208x; 2.5208x over previous
#include <cuda_runtime.h>
#include <math.h>
#include <stdint.h>

#define NOBS 72000
#define NBUK 9000
#define LMAXX 8
#define DIM 256
#define NTOK 8
#define DH 32
#define DEPTH 8
#define FFND 1024
#define OUTD 2048
#define CLAT 512

// ---------------- scratch (device globals: no allocation allowed) ----------
static __device__ float g_h  [NOBS * DIM];
static __device__ float g_ctx[NOBS * DIM];
static __device__ float g_q  [NOBS * DIM];
static __device__ float g_k  [NOBS * DIM];
static __device__ float g_v  [NOBS * DIM];
static __device__ float g_o  [NOBS * DIM];
static __device__ float g_trx[NOBS * DIM];
static __device__ float g_ln [NOBS * DIM];
static __device__ float g_ffn[NOBS * FFND];
static __device__ int   g_cnt[NBUK];
static __device__ int   g_row[NOBS];

__device__ __forceinline__ float gelu_tanh(float x) {
    float x3 = x * x * x;
    float t = tanhf(0.7978845608028654f * (x + 0.044715f * x3));
    return 0.5f * x * (1.0f + t);
}

__device__ __forceinline__ float to_tf32(float x) {
    uint32_t u;
    asm("cvt.rna.tf32.f32 %0, %1;" : "=r"(u) : "f"(x));
    return __uint_as_float(u);
}

__device__ __forceinline__ void mma_tf32(float* c, const uint32_t* a,
                                         uint32_t b0, uint32_t b1) {
    asm volatile(
        "mma.sync.aligned.m16n8k8.row.col.f32.tf32.tf32.f32 "
        "{%0,%1,%2,%3},{%4,%5,%6,%7},{%8,%9},{%0,%1,%2,%3};\n"
        : "+f"(c[0]), "+f"(c[1]), "+f"(c[2]), "+f"(c[3])
        : "r"(a[0]), "r"(a[1]), "r"(a[2]), "r"(a[3]), "r"(b0), "r"(b1));
}

// ---------------- TF32 tensor-core GEMM ------------------------------------
// C[M,N] = act(A[M,K] @ B[K,N] + bias) [+ res] [gated]. Row-major.
// BM=128, BN=128, BK=32. 256 threads, 4(M)x2(N) warps, warp tile 32x64.
// Requires N % 128 == 0, K % 32 == 0. M guarded.
#define AS_STRIDE 36
#define BS_STRIDE 136
#define AS_HALF (128 * AS_STRIDE)
#define BS_HALF (32 * BS_STRIDE)
#define GEMM_SMEM ((AS_HALF + BS_HALF) * 2 * 4)

__global__ __launch_bounds__(256, 2)
void k_gemm_tc(const float* __restrict__ A, const float* __restrict__ B,
               const float* __restrict__ bias, const float* __restrict__ res,
               const int* __restrict__ gate, float* __restrict__ C,
               int M, int N, int K, int act)
{
    extern __shared__ float smem[];
    float* As = smem;                   // [2][128][36]
    float* Bs = smem + 2 * AS_HALF;     // [2][32][136]

    const int tid = threadIdx.x;
    const int lane = tid & 31;
    const int warp = tid >> 5;
    const int wm = warp & 3;            // 0..3 (M)
    const int wn = warp >> 2;           // 0..1 (N)
    const int rowBase = blockIdx.y << 7;
    const int colBase = blockIdx.x << 7;

    float acc[2][8][4];
#pragma unroll
    for (int i = 0; i < 2; i++)
#pragma unroll
        for (int j = 0; j < 8; j++)
#pragma unroll
            for (int l = 0; l < 4; l++) acc[i][j][l] = 0.0f;

    // per-thread tile-copy coordinates
    const int aRow = tid >> 1;               // with r offset: f = tid + r*256
    (void)aRow;
    float4 pa[4], pb[4];

    auto load_tiles = [&](int kt) {
#pragma unroll
        for (int r = 0; r < 4; r++) {
            int f = tid + (r << 8);          // 0..1023
            int row = f >> 3, c4 = f & 7;    // A: 128 rows x 8 float4
            int gm = rowBase + row;
            pa[r] = (gm < M) ? *(const float4*)(A + (size_t)gm * K + kt + (c4 << 2))
                             : make_float4(0.f, 0.f, 0.f, 0.f);
        }
#pragma unroll
        for (int r = 0; r < 4; r++) {
            int f = tid + (r << 8);
            int row = f >> 5, c4 = f & 31;   // B: 32 rows x 32 float4
            pb[r] = *(const float4*)(B + (size_t)(kt + row) * N + colBase + (c4 << 2));
        }
    };

    auto store_tiles = [&](int s) {
        float* a = As + s * AS_HALF;
        float* b = Bs + s * BS_HALF;
#pragma unroll
        for (int r = 0; r < 4; r++) {
            int f = tid + (r << 8);
            int row = f >> 3, c = (f & 7) << 2;
            float* p = a + row * AS_STRIDE + c;
            p[0] = to_tf32(pa[r].x); p[1] = to_tf32(pa[r].y);
            p[2] = to_tf32(pa[r].z); p[3] = to_tf32(pa[r].w);
        }
#pragma unroll
        for (int r = 0; r < 4; r++) {
            int f = tid + (r << 8);
            int row = f >> 5, c = (f & 31) << 2;
            float* p = b + row * BS_STRIDE + c;
            p[0] = to_tf32(pb[r].x); p[1] = to_tf32(pb[r].y);
            p[2] = to_tf32(pb[r].z); p[3] = to_tf32(pb[r].w);
        }
    };

    auto compute = [&](int s) {
        const float* a0 = As + s * AS_HALF + (wm * 32 + (lane >> 2)) * AS_STRIDE + (lane & 3);
        const float* bb = Bs + s * BS_HALF + (lane & 3) * BS_STRIDE + wn * 64 + (lane >> 2);
#pragma unroll
        for (int ks = 0; ks < 4; ks++) {
            const float* ap = a0 + ks * 8;
            uint32_t af[2][4];
#pragma unroll
            for (int mt = 0; mt < 2; mt++) {
                const float* p = ap + mt * 16 * AS_STRIDE;
                af[mt][0] = __float_as_uint(p[0]);
                af[mt][1] = __float_as_uint(p[8 * AS_STRIDE]);
                af[mt][2] = __float_as_uint(p[4]);
                af[mt][3] = __float_as_uint(p[8 * AS_STRIDE + 4]);
            }
            const float* bp = bb + ks * 8 * BS_STRIDE;
#pragma unroll
            for (int nt = 0; nt < 8; nt++) {
                uint32_t b0 = __float_as_uint(bp[nt * 8]);
                uint32_t b1 = __float_as_uint(bp[4 * BS_STRIDE + nt * 8]);
                mma_tf32(acc[0][nt], af[0], b0, b1);
                mma_tf32(acc[1][nt], af[1], b0, b1);
            }
        }
    };

    // pipeline: prefetch tile0 -> smem buf0
    load_tiles(0);
    store_tiles(0);
    __syncthreads();
    int s = 0;
    for (int kt = 32; kt <= K; kt += 32) {
        bool more = kt < K;
        if (more) load_tiles(kt);
        compute(s);
        if (more) {
            store_tiles(s ^ 1);
            __syncthreads();
            s ^= 1;
        }
    }

    // ---------------- epilogue ----------------
#pragma unroll
    for (int mt = 0; mt < 2; mt++) {
#pragma unroll
        for (int half = 0; half < 2; half++) {
            int gm = rowBase + wm * 32 + mt * 16 + (lane >> 2) + half * 8;
            if (gm >= M) continue;
            bool gz = (gate && gate[gm] == 0);
#pragma unroll
            for (int nt = 0; nt < 8; nt++) {
                int gn = colBase + wn * 64 + nt * 8 + ((lane & 3) << 1);
                float cx = acc[mt][nt][half * 2 + 0];
                float cy = acc[mt][nt][half * 2 + 1];
                if (bias) {
                    float2 bv = *(const float2*)(bias + gn);
                    cx += bv.x; cy += bv.y;
                }
                if (act) { cx = gelu_tanh(cx); cy = gelu_tanh(cy); }
                if (res) {
                    float2 rv = *(const float2*)(res + (size_t)gm * N + gn);
                    cx += rv.x; cy += rv.y;
                }
                if (gz) { cx = 0.f; cy = 0.f; }
                *(float2*)(C + (size_t)gm * N + gn) = make_float2(cx, cy);
            }
        }
    }
}

// ---------------- layernorm: one warp per 256-wide row ----------------------
__global__ void k_ln(const float* __restrict__ X, float* __restrict__ Y,
                     const float* __restrict__ G, const float* __restrict__ Bb)
{
    int row  = blockIdx.x * 8 + (threadIdx.x >> 5);
    int lane = threadIdx.x & 31;
    const float* x = X + (size_t)row * DIM;
    float v[8];
    float s = 0.f;
#pragma unroll
    for (int r = 0; r < 8; r++) { v[r] = x[lane + (r << 5)]; s += v[r]; }
#pragma unroll
    for (int off = 16; off; off >>= 1) s += __shfl_xor_sync(0xffffffffu, s, off);
    float mean = s * (1.0f / 256.0f);
    float vs = 0.f;
#pragma unroll
    for (int r = 0; r < 8; r++) { float d = v[r] - mean; vs = fmaf(d, d, vs); }
#pragma unroll
    for (int off = 16; off; off >>= 1) vs += __shfl_xor_sync(0xffffffffu, vs, off);
    float inv = rsqrtf(vs * (1.0f / 256.0f) + 1e-5f);
    float* y = Y + (size_t)row * DIM;
#pragma unroll
    for (int r = 0; r < 8; r++) {
        int c = lane + (r << 5);
        y[c] = (v[r] - mean) * inv * G[c] + Bb[c];
    }
}

// ---------------- per-bucket cross attention (NTOK=8 q, LMAX=8 kv) ----------
__global__ void k_attn(const float* __restrict__ Q, const float* __restrict__ Kx,
                       const float* __restrict__ V, float* __restrict__ O)
{
    __shared__ __align__(16) float sQ[NTOK * DIM];
    __shared__ __align__(16) float sK[LMAXX * DIM];
    __shared__ __align__(16) float sV[LMAXX * DIM];
    int b = blockIdx.x;
    int tid = threadIdx.x;  // 64 threads
    const float4* q4 = (const float4*)(Q + (size_t)b * NTOK * DIM);
    const float4* k4 = (const float4*)(Kx + (size_t)b * LMAXX * DIM);
    const float4* v4 = (const float4*)(V + (size_t)b * LMAXX * DIM);
#pragma unroll
    for (int r = 0; r < 8; r++) {
        ((float4*)sQ)[tid + r * 64] = q4[tid + r * 64];
        ((float4*)sK)[tid + r * 64] = k4[tid + r * 64];
        ((float4*)sV)[tid + r * 64] = v4[tid + r * 64];
    }
    int cnt = g_cnt[b];
    __syncthreads();

    int h = tid >> 3, qi = tid & 7;
    const float* qp = sQ + qi * DIM + h * DH;
    float qr[DH];
#pragma unroll
    for (int d = 0; d < DH; d++) qr[d] = qp[d];

    float sc[LMAXX];
    float mx = -1e30f;
#pragma unroll
    for (int j = 0; j < LMAXX; j++) {
        const float* kp = sK + j * DIM + h * DH;
        float s = 0.f;
#pragma unroll
        for (int d = 0; d < DH; d++) s = fmaf(qr[d], kp[d], s);
        s = s * 0.17677669529663689f;
        if (j >= cnt) s -= 1e9f;
        sc[j] = s;
        mx = fmaxf(mx, s);
    }
    float den = 0.f;
#pragma unroll
    for (int j = 0; j < LMAXX; j++) { sc[j] = expf(sc[j] - mx); den += sc[j]; }
    float inv = 1.0f / den;
    float o[DH];
#pragma unroll
    for (int d = 0; d < DH; d++) o[d] = 0.f;
#pragma unroll
    for (int j = 0; j < LMAXX; j++) {
        float a = sc[j] * inv;
        const float* vp = sV + j * DIM + h * DH;
#pragma unroll
        for (int d = 0; d < DH; d++) o[d] = fmaf(a, vp[d], o[d]);
    }
    float* op = O + (size_t)(b * NTOK + qi) * DIM + h * DH;
#pragma unroll
    for (int d = 0; d < DH; d++) op[d] = o[d];
}

// ---------------- dispatch helpers ------------------------------------------
__global__ void k_reset_cnt()
{
    int i = blockIdx.x * blockDim.x + threadIdx.x;
    if (i < NBUK) g_cnt[i] = 0;
}

__global__ void k_flatpos(const int* __restrict__ li)
{
    int i = blockIdx.x * blockDim.x + threadIdx.x;
    if (i >= NOBS) return;
    int d = li[3 * i], hh = li[3 * i + 1], w = li[3 * i + 2];
    int f = d * 1800 + hh * 60 + w;
    int pos = atomicAdd(&g_cnt[f], 1);
    g_row[i] = (pos < LMAXX) ? (f * LMAXX + pos) : -1;
}

__global__ void k_scatter()
{
    int wid  = (blockIdx.x * blockDim.x + threadIdx.x) >> 5;
    int lane = threadIdx.x & 31;
    if (wid >= NOBS) return;
    int dst = g_row[wid];
    if (dst < 0) return;
    const float4* src = (const float4*)(g_h + (size_t)wid * DIM);
    float4* dp = (float4*)(g_ctx + (size_t)dst * DIM);
    dp[lane]      = src[lane];
    dp[lane + 32] = src[lane + 32];
}

__global__ void k_init_trx(const float* __restrict__ bg)
{
    int idx = blockIdx.x * blockDim.x + threadIdx.x;
    if (idx >= NOBS * DIM / 4) return;
    int row = idx >> 6;
    int t   = row & 7;
    int c4  = idx & 63;
    ((float4*)g_trx)[idx] = ((const float4*)bg)[t * 64 + c4];
}

// ---------------- launch ------------------------------------------------------
extern "C" void kernel_launch(void* const* d_in, const int* in_sizes, int n_in,
                              void* d_out, int out_size)
{
    const float* x     = (const float*)d_in[0];
    const int*   li    = (const int*)  d_in[1];
    const float* mlp_w = (const float*)d_in[2];
    const float* mlp_b = (const float*)d_in[3];
    const float* bg    = (const float*)d_in[4];
    const float* ln1g  = (const float*)d_in[5];
    const float* ln1b  = (const float*)d_in[6];
    const float* wq    = (const float*)d_in[7];
    const float* bq    = (const float*)d_in[8];
    const float* wk    = (const float*)d_in[9];
    const float* bk    = (const float*)d_in[10];
    const float* wv    = (const float*)d_in[11];
    const float* bv    = (const float*)d_in[12];
    const float* wo    = (const float*)d_in[13];
    const float* bo    = (const float*)d_in[14];
    const float* ln2g  = (const float*)d_in[15];
    const float* ln2b  = (const float*)d_in[16];
    const float* w1    = (const float*)d_in[17];
    const float* b1    = (const float*)d_in[18];
    const float* w2    = (const float*)d_in[19];
    const float* b2    = (const float*)d_in[20];
    const float* pw    = (const float*)d_in[21];
    const float* pb    = (const float*)d_in[22];
    float* out = (float*)d_out;
    (void)in_sizes; (void)n_in; (void)out_size;

    float *ph, *pctx, *pq, *pk, *pv, *po, *ptrx, *pln, *pffn;
    int *pcnt;
    cudaGetSymbolAddress((void**)&ph,   g_h);
    cudaGetSymbolAddress((void**)&pctx, g_ctx);
    cudaGetSymbolAddress((void**)&pq,   g_q);
    cudaGetSymbolAddress((void**)&pk,   g_k);
    cudaGetSymbolAddress((void**)&pv,   g_v);
    cudaGetSymbolAddress((void**)&po,   g_o);
    cudaGetSymbolAddress((void**)&ptrx, g_trx);
    cudaGetSymbolAddress((void**)&pln,  g_ln);
    cudaGetSymbolAddress((void**)&pffn, g_ffn);
    cudaGetSymbolAddress((void**)&pcnt, g_cnt);

    cudaFuncSetAttribute(k_gemm_tc, cudaFuncAttributeMaxDynamicSharedMemorySize,
                         GEMM_SMEM);

    auto gemm = [](const float* A, const float* B, const float* bias,
                   const float* res, const int* gate, float* C,
                   int M, int N, int K, int act) {
        dim3 grid(N / 128, (M + 127) / 128);
        k_gemm_tc<<<grid, 256, GEMM_SMEM>>>(A, B, bias, res, gate, C, M, N, K, act);
    };

    // --- obs feature MLP: fc1 -> gelu -> fc2 -> gelu -> fc3 ---
    gemm(x,   mlp_w,             mlp_b,       nullptr, nullptr, pln, NOBS, DIM, DIM, 1);
    gemm(pln, mlp_w + 65536,     mlp_b + 256, nullptr, nullptr, pq,  NOBS, DIM, DIM, 1);
    gemm(pq,  mlp_w + 2 * 65536, mlp_b + 512, nullptr, nullptr, ph,  NOBS, DIM, DIM, 0);

    // --- dispatch into [NB, LMAX, DIM] buckets ---
    k_reset_cnt<<<(NBUK + 255) / 256, 256>>>();
    k_flatpos<<<(NOBS + 255) / 256, 256>>>(li);
    k_scatter<<<NOBS / 8, 256>>>();
    k_init_trx<<<NOBS * DIM / 4 / 256, 256>>>(bg);

    // --- 8-layer cross-attention transformer ---
    for (int l = 0; l < DEPTH; l++) {
        k_ln<<<NBUK, 256>>>(ptrx, pln, ln1g + l * DIM, ln1b + l * DIM);
        gemm(pln,  wq + l * 65536, bq + l * DIM, nullptr, nullptr, pq, NOBS, DIM, DIM, 0);
        gemm(pctx, wk + l * 65536, bk + l * DIM, nullptr, nullptr, pk, NOBS, DIM, DIM, 0);
        gemm(pctx, wv + l * 65536, bv + l * DIM, nullptr, nullptr, pv, NOBS, DIM, DIM, 0);
        k_attn<<<NBUK, 64>>>(pq, pk, pv, po);
        gemm(po, wo + l * 65536, bo + l * DIM, ptrx, nullptr, ptrx, NOBS, DIM, DIM, 0);
        k_ln<<<NBUK, 256>>>(ptrx, pln, ln2g + l * DIM, ln2b + l * DIM);
        gemm(pln,  w1 + l * DIM * FFND, b1 + l * FFND, nullptr, nullptr, pffn, NOBS, FFND, DIM, 1);
        gemm(pffn, w2 + l * FFND * DIM, b2 + l * DIM,  ptrx,    nullptr, ptrx, NOBS, DIM, FFND, 0);
    }

    // --- final projection, gated by occupancy ---
    gemm(ptrx, pw, pb, nullptr, pcnt, out, NBUK, CLAT, OUTD, 0);
}

// round 3
// speedup vs baseline: 2.7586x; 1.0943x over previous
#include <cuda_runtime.h>
#include <math.h>
#include <stdint.h>

#define NOBS 72000
#define NBUK 9000
#define LMAXX 8
#define DIM 256
#define NTOK 8
#define DH 32
#define DEPTH 8
#define FFND 1024
#define OUTD 2048
#define CLAT 512

// ---------------- scratch (device globals: no allocation allowed) ----------
static __device__ float g_h  [NOBS * DIM];
static __device__ float g_ctx[NOBS * DIM];
static __device__ float g_q  [NOBS * DIM];
static __device__ float g_k  [NOBS * DIM];
static __device__ float g_v  [NOBS * DIM];
static __device__ float g_o  [NOBS * DIM];
static __device__ float g_trx[NOBS * DIM];
static __device__ float g_ln [NOBS * DIM];
static __device__ float g_ffn[NOBS * FFND];
static __device__ float g_wt [7536640];     // tf32-rounded weights
static __device__ int   g_cnt[NBUK];
static __device__ int   g_row[NOBS];

// offsets into g_wt
#define OFF_MLPW 0
#define OFF_WQ   196608
#define OFF_WK   720896
#define OFF_WV   1245184
#define OFF_WO   1769472
#define OFF_W1   2293760
#define OFF_W2   4390912
#define OFF_PROJ 6488064

__device__ __forceinline__ float gelu_tanh(float x) {
    float x3 = x * x * x;
    float t = tanhf(0.7978845608028654f * (x + 0.044715f * x3));
    return 0.5f * x * (1.0f + t);
}

__device__ __forceinline__ float to_tf32(float x) {
    uint32_t u;
    asm("cvt.rna.tf32.f32 %0, %1;" : "=r"(u) : "f"(x));
    return __uint_as_float(u);
}

__device__ __forceinline__ void mma_tf32(float* c, const uint32_t* a,
                                         uint32_t b0, uint32_t b1) {
    asm volatile(
        "mma.sync.aligned.m16n8k8.row.col.f32.tf32.tf32.f32 "
        "{%0,%1,%2,%3},{%4,%5,%6,%7},{%8,%9},{%0,%1,%2,%3};\n"
        : "+f"(c[0]), "+f"(c[1]), "+f"(c[2]), "+f"(c[3])
        : "r"(a[0]), "r"(a[1]), "r"(a[2]), "r"(a[3]), "r"(b0), "r"(b1));
}

__device__ __forceinline__ void cp_async16(uint32_t saddr, const void* g, int srcB) {
    asm volatile("cp.async.cg.shared.global [%0], [%1], 16, %2;\n"
                 :: "r"(saddr), "l"(g), "r"(srcB));
}
__device__ __forceinline__ void cp_commit() {
    asm volatile("cp.async.commit_group;\n");
}
template <int N>
__device__ __forceinline__ void cp_wait() {
    asm volatile("cp.async.wait_group %0;\n" :: "n"(N));
}

// ---------------- TF32 tensor-core GEMM, cp.async 3-stage -------------------
// C[M,N] = act(A@B + bias) [+res] [gated]. A,B pre-rounded to tf32 values.
// BM=128, BN=128, BK=32, 256 thr, 4(M)x2(N) warps (warp tile 32x64).
#define STAGES 3
#define AS_STRIDE 36
#define BS_STRIDE 136
#define AS_SZ (128 * AS_STRIDE)
#define BS_SZ (32 * BS_STRIDE)
#define GEMM_SMEM (STAGES * (AS_SZ + BS_SZ) * 4)

__global__ __launch_bounds__(256, 2)
void k_gemm_tc(const float* __restrict__ A, const float* __restrict__ B,
               const float* __restrict__ bias, const float* __restrict__ res,
               const int* __restrict__ gate, float* __restrict__ C,
               int M, int N, int K, int act)
{
    extern __shared__ float smem[];
    float* As = smem;                       // [STAGES][128][36]
    float* Bs = smem + STAGES * AS_SZ;      // [STAGES][32][136]

    const int tid = threadIdx.x;
    const int lane = tid & 31;
    const int warp = tid >> 5;
    const int wm = warp & 3;
    const int wn = warp >> 2;
    const int rowBase = blockIdx.y << 7;
    const int colBase = blockIdx.x << 7;

    const uint32_t sAs = (uint32_t)__cvta_generic_to_shared(As);
    const uint32_t sBs = (uint32_t)__cvta_generic_to_shared(Bs);

    float acc[2][8][4];
#pragma unroll
    for (int i = 0; i < 2; i++)
#pragma unroll
        for (int j = 0; j < 8; j++)
#pragma unroll
            for (int l = 0; l < 4; l++) acc[i][j][l] = 0.0f;

    auto load_stage = [&](int kt, int s) {
        uint32_t ab = sAs + s * (AS_SZ * 4);
        uint32_t bb = sBs + s * (BS_SZ * 4);
#pragma unroll
        for (int r = 0; r < 4; r++) {
            int f = tid + (r << 8);
            int row = f >> 3, c4 = f & 7;
            int gm = rowBase + row;
            int gmc = gm < M ? gm : M - 1;
            cp_async16(ab + (row * AS_STRIDE + (c4 << 2)) * 4,
                       A + (size_t)gmc * K + kt + (c4 << 2),
                       gm < M ? 16 : 0);
        }
#pragma unroll
        for (int r = 0; r < 4; r++) {
            int f = tid + (r << 8);
            int row = f >> 5, c4 = f & 31;
            cp_async16(bb + (row * BS_STRIDE + (c4 << 2)) * 4,
                       B + (size_t)(kt + row) * N + colBase + (c4 << 2), 16);
        }
        cp_commit();
    };

    auto compute = [&](int s) {
        const float* a0 = As + s * AS_SZ + (wm * 32 + (lane >> 2)) * AS_STRIDE + (lane & 3);
        const float* bb = Bs + s * BS_SZ + (lane & 3) * BS_STRIDE + wn * 64 + (lane >> 2);
#pragma unroll
        for (int ks = 0; ks < 4; ks++) {
            const float* ap = a0 + ks * 8;
            uint32_t af[2][4];
#pragma unroll
            for (int mt = 0; mt < 2; mt++) {
                const float* p = ap + mt * 16 * AS_STRIDE;
                af[mt][0] = __float_as_uint(p[0]);
                af[mt][1] = __float_as_uint(p[8 * AS_STRIDE]);
                af[mt][2] = __float_as_uint(p[4]);
                af[mt][3] = __float_as_uint(p[8 * AS_STRIDE + 4]);
            }
            const float* bp = bb + ks * 8 * BS_STRIDE;
#pragma unroll
            for (int nt = 0; nt < 8; nt++) {
                uint32_t b0 = __float_as_uint(bp[nt * 8]);
                uint32_t b1 = __float_as_uint(bp[4 * BS_STRIDE + nt * 8]);
                mma_tf32(acc[0][nt], af[0], b0, b1);
                mma_tf32(acc[1][nt], af[1], b0, b1);
            }
        }
    };

    const int T = K >> 5;
    load_stage(0, 0);
    load_stage(32, 1);
    for (int t = 0; t < T; t++) {
        cp_wait<STAGES - 2>();
        __syncthreads();
        if (t + STAGES - 1 < T) {
            int tn = t + STAGES - 1;
            load_stage(tn << 5, tn % STAGES);
        }
        compute(t % STAGES);
    }

    // ---------------- epilogue ----------------
#pragma unroll
    for (int mt = 0; mt < 2; mt++) {
#pragma unroll
        for (int half = 0; half < 2; half++) {
            int gm = rowBase + wm * 32 + mt * 16 + (lane >> 2) + half * 8;
            if (gm >= M) continue;
            bool gz = (gate && gate[gm] == 0);
#pragma unroll
            for (int nt = 0; nt < 8; nt++) {
                int gn = colBase + wn * 64 + nt * 8 + ((lane & 3) << 1);
                float cx = acc[mt][nt][half * 2 + 0];
                float cy = acc[mt][nt][half * 2 + 1];
                if (bias) {
                    float2 bv = *(const float2*)(bias + gn);
                    cx += bv.x; cy += bv.y;
                }
                if (act) {
                    cx = to_tf32(gelu_tanh(cx));   // output feeds next GEMM
                    cy = to_tf32(gelu_tanh(cy));
                }
                if (res) {
                    float2 rv = *(const float2*)(res + (size_t)gm * N + gn);
                    cx += rv.x; cy += rv.y;
                }
                if (gz) { cx = 0.f; cy = 0.f; }
                *(float2*)(C + (size_t)gm * N + gn) = make_float2(cx, cy);
            }
        }
    }
}

// ---------------- layernorm (output rounded to tf32: feeds GEMM A) ---------
__global__ void k_ln(const float* __restrict__ X, float* __restrict__ Y,
                     const float* __restrict__ G, const float* __restrict__ Bb)
{
    int row  = blockIdx.x * 8 + (threadIdx.x >> 5);
    int lane = threadIdx.x & 31;
    const float* x = X + (size_t)row * DIM;
    float v[8];
    float s = 0.f;
#pragma unroll
    for (int r = 0; r < 8; r++) { v[r] = x[lane + (r << 5)]; s += v[r]; }
#pragma unroll
    for (int off = 16; off; off >>= 1) s += __shfl_xor_sync(0xffffffffu, s, off);
    float mean = s * (1.0f / 256.0f);
    float vs = 0.f;
#pragma unroll
    for (int r = 0; r < 8; r++) { float d = v[r] - mean; vs = fmaf(d, d, vs); }
#pragma unroll
    for (int off = 16; off; off >>= 1) vs += __shfl_xor_sync(0xffffffffu, vs, off);
    float inv = rsqrtf(vs * (1.0f / 256.0f) + 1e-5f);
    float* y = Y + (size_t)row * DIM;
#pragma unroll
    for (int r = 0; r < 8; r++) {
        int c = lane + (r << 5);
        y[c] = to_tf32((v[r] - mean) * inv * G[c] + Bb[c]);
    }
}

// ---------------- per-bucket cross attention --------------------------------
__global__ void k_attn(const float* __restrict__ Q, const float* __restrict__ Kx,
                       const float* __restrict__ V, float* __restrict__ O)
{
    __shared__ __align__(16) float sQ[NTOK * DIM];
    __shared__ __align__(16) float sK[LMAXX * DIM];
    __shared__ __align__(16) float sV[LMAXX * DIM];
    int b = blockIdx.x;
    int tid = threadIdx.x;  // 64 threads
    const float4* q4 = (const float4*)(Q + (size_t)b * NTOK * DIM);
    const float4* k4 = (const float4*)(Kx + (size_t)b * LMAXX * DIM);
    const float4* v4 = (const float4*)(V + (size_t)b * LMAXX * DIM);
#pragma unroll
    for (int r = 0; r < 8; r++) {
        ((float4*)sQ)[tid + r * 64] = q4[tid + r * 64];
        ((float4*)sK)[tid + r * 64] = k4[tid + r * 64];
        ((float4*)sV)[tid + r * 64] = v4[tid + r * 64];
    }
    int cnt = g_cnt[b];
    __syncthreads();

    int h = tid >> 3, qi = tid & 7;
    const float* qp = sQ + qi * DIM + h * DH;
    float qr[DH];
#pragma unroll
    for (int d = 0; d < DH; d++) qr[d] = qp[d];

    float sc[LMAXX];
    float mx = -1e30f;
#pragma unroll
    for (int j = 0; j < LMAXX; j++) {
        const float* kp = sK + j * DIM + h * DH;
        float s = 0.f;
#pragma unroll
        for (int d = 0; d < DH; d++) s = fmaf(qr[d], kp[d], s);
        s = s * 0.17677669529663689f;
        if (j >= cnt) s -= 1e9f;
        sc[j] = s;
        mx = fmaxf(mx, s);
    }
    float den = 0.f;
#pragma unroll
    for (int j = 0; j < LMAXX; j++) { sc[j] = expf(sc[j] - mx); den += sc[j]; }
    float inv = 1.0f / den;
    float o[DH];
#pragma unroll
    for (int d = 0; d < DH; d++) o[d] = 0.f;
#pragma unroll
    for (int j = 0; j < LMAXX; j++) {
        float a = sc[j] * inv;
        const float* vp = sV + j * DIM + h * DH;
#pragma unroll
        for (int d = 0; d < DH; d++) o[d] = fmaf(a, vp[d], o[d]);
    }
    float* op = O + (size_t)(b * NTOK + qi) * DIM + h * DH;
#pragma unroll
    for (int d = 0; d < DH; d++) op[d] = to_tf32(o[d]);   // feeds wo GEMM
}

// ---------------- dispatch helpers ------------------------------------------
__global__ void k_reset_cnt()
{
    int i = blockIdx.x * blockDim.x + threadIdx.x;
    if (i < NBUK) g_cnt[i] = 0;
}

__global__ void k_flatpos(const int* __restrict__ li)
{
    int i = blockIdx.x * blockDim.x + threadIdx.x;
    if (i >= NOBS) return;
    int d = li[3 * i], hh = li[3 * i + 1], w = li[3 * i + 2];
    int f = d * 1800 + hh * 60 + w;
    int pos = atomicAdd(&g_cnt[f], 1);
    g_row[i] = (pos < LMAXX) ? (f * LMAXX + pos) : -1;
}

__global__ void k_scatter()
{
    int wid  = (blockIdx.x * blockDim.x + threadIdx.x) >> 5;
    int lane = threadIdx.x & 31;
    if (wid >= NOBS) return;
    int dst = g_row[wid];
    if (dst < 0) return;
    const float4* src = (const float4*)(g_h + (size_t)wid * DIM);
    float4* dp = (float4*)(g_ctx + (size_t)dst * DIM);
#pragma unroll
    for (int r = 0; r < 2; r++) {
        float4 v = src[lane + r * 32];
        v.x = to_tf32(v.x); v.y = to_tf32(v.y);
        v.z = to_tf32(v.z); v.w = to_tf32(v.w);
        dp[lane + r * 32] = v;
    }
}

__global__ void k_init_trx(const float* __restrict__ bg)
{
    int idx = blockIdx.x * blockDim.x + threadIdx.x;
    if (idx >= NOBS * DIM / 4) return;
    int row = idx >> 6;
    int t   = row & 7;
    int c4  = idx & 63;
    ((float4*)g_trx)[idx] = ((const float4*)bg)[t * 64 + c4];
}

// ---------------- tf32 rounding pass (weights / inputs) ---------------------
__global__ void k_round4(const float4* __restrict__ s, float4* __restrict__ d, int n4)
{
    int i = blockIdx.x * blockDim.x + threadIdx.x;
    if (i >= n4) return;
    float4 v = s[i];
    v.x = to_tf32(v.x); v.y = to_tf32(v.y);
    v.z = to_tf32(v.z); v.w = to_tf32(v.w);
    d[i] = v;
}

// ---------------- launch ------------------------------------------------------
extern "C" void kernel_launch(void* const* d_in, const int* in_sizes, int n_in,
                              void* d_out, int out_size)
{
    const float* x     = (const float*)d_in[0];
    const int*   li    = (const int*)  d_in[1];
    const float* mlp_w = (const float*)d_in[2];
    const float* mlp_b = (const float*)d_in[3];
    const float* bg    = (const float*)d_in[4];
    const float* ln1g  = (const float*)d_in[5];
    const float* ln1b  = (const float*)d_in[6];
    const float* wq    = (const float*)d_in[7];
    const float* bq    = (const float*)d_in[8];
    const float* wk    = (const float*)d_in[9];
    const float* bk    = (const float*)d_in[10];
    const float* wv    = (const float*)d_in[11];
    const float* bv    = (const float*)d_in[12];
    const float* wo    = (const float*)d_in[13];
    const float* bo    = (const float*)d_in[14];
    const float* ln2g  = (const float*)d_in[15];
    const float* ln2b  = (const float*)d_in[16];
    const float* w1    = (const float*)d_in[17];
    const float* b1    = (const float*)d_in[18];
    const float* w2    = (const float*)d_in[19];
    const float* b2    = (const float*)d_in[20];
    const float* pw    = (const float*)d_in[21];
    const float* pb    = (const float*)d_in[22];
    float* out = (float*)d_out;
    (void)in_sizes; (void)n_in; (void)out_size;

    float *ph, *pctx, *pq, *pk, *pv, *po, *ptrx, *pln, *pffn, *pwt;
    int *pcnt;
    cudaGetSymbolAddress((void**)&ph,   g_h);
    cudaGetSymbolAddress((void**)&pctx, g_ctx);
    cudaGetSymbolAddress((void**)&pq,   g_q);
    cudaGetSymbolAddress((void**)&pk,   g_k);
    cudaGetSymbolAddress((void**)&pv,   g_v);
    cudaGetSymbolAddress((void**)&po,   g_o);
    cudaGetSymbolAddress((void**)&ptrx, g_trx);
    cudaGetSymbolAddress((void**)&pln,  g_ln);
    cudaGetSymbolAddress((void**)&pffn, g_ffn);
    cudaGetSymbolAddress((void**)&pwt,  g_wt);
    cudaGetSymbolAddress((void**)&pcnt, g_cnt);

    cudaFuncSetAttribute(k_gemm_tc, cudaFuncAttributeMaxDynamicSharedMemorySize,
                         GEMM_SMEM);

    auto rnd = [](const float* s, float* d, int n) {
        int n4 = n >> 2;
        k_round4<<<(n4 + 255) / 256, 256>>>((const float4*)s, (float4*)d, n4);
    };

    // --- pre-round weights & x to tf32 values ---
    rnd(mlp_w, pwt + OFF_MLPW, 3 * 65536);
    rnd(wq,    pwt + OFF_WQ,   8 * 65536);
    rnd(wk,    pwt + OFF_WK,   8 * 65536);
    rnd(wv,    pwt + OFF_WV,   8 * 65536);
    rnd(wo,    pwt + OFF_WO,   8 * 65536);
    rnd(w1,    pwt + OFF_W1,   8 * 262144);
    rnd(w2,    pwt + OFF_W2,   8 * 262144);
    rnd(pw,    pwt + OFF_PROJ, OUTD * CLAT);
    rnd(x,     po,             NOBS * DIM);

    auto gemm = [](const float* A, const float* B, const float* bias,
                   const float* res, const int* gate, float* C,
                   int M, int N, int K, int act) {
        dim3 grid(N / 128, (M + 127) / 128);
        k_gemm_tc<<<grid, 256, GEMM_SMEM>>>(A, B, bias, res, gate, C, M, N, K, act);
    };

    // --- obs feature MLP: fc1 -> gelu -> fc2 -> gelu -> fc3 ---
    gemm(po,  pwt + OFF_MLPW,             mlp_b,       nullptr, nullptr, pln, NOBS, DIM, DIM, 1);
    gemm(pln, pwt + OFF_MLPW + 65536,     mlp_b + 256, nullptr, nullptr, pq,  NOBS, DIM, DIM, 1);
    gemm(pq,  pwt + OFF_MLPW + 2 * 65536, mlp_b + 512, nullptr, nullptr, ph,  NOBS, DIM, DIM, 0);

    // --- dispatch into [NB, LMAX, DIM] buckets ---
    k_reset_cnt<<<(NBUK + 255) / 256, 256>>>();
    k_flatpos<<<(NOBS + 255) / 256, 256>>>(li);
    k_scatter<<<NOBS / 8, 256>>>();
    k_init_trx<<<NOBS * DIM / 4 / 256, 256>>>(bg);

    // --- 8-layer cross-attention transformer ---
    for (int l = 0; l < DEPTH; l++) {
        k_ln<<<NBUK, 256>>>(ptrx, pln, ln1g + l * DIM, ln1b + l * DIM);
        gemm(pln,  pwt + OFF_WQ + l * 65536, bq + l * DIM, nullptr, nullptr, pq, NOBS, DIM, DIM, 0);
        gemm(pctx, pwt + OFF_WK + l * 65536, bk + l * DIM, nullptr, nullptr, pk, NOBS, DIM, DIM, 0);
        gemm(pctx, pwt + OFF_WV + l * 65536, bv + l * DIM, nullptr, nullptr, pv, NOBS, DIM, DIM, 0);
        k_attn<<<NBUK, 64>>>(pq, pk, pv, po);
        gemm(po, pwt + OFF_WO + l * 65536, bo + l * DIM, ptrx, nullptr, ptrx, NOBS, DIM, DIM, 0);
        k_ln<<<NBUK, 256>>>(ptrx, pln, ln2g + l * DIM, ln2b + l * DIM);
        gemm(pln,  pwt + OFF_W1 + l * DIM * FFND, b1 + l * FFND, nullptr, nullptr, pffn, NOBS, FFND, DIM, 1);
        gemm(pffn, pwt + OFF_W2 + l * FFND * DIM, b2 + l * DIM,  ptrx,    nullptr, ptrx, NOBS, DIM, FFND, 0);
    }

    // --- final projection, gated by occupancy (round trx first) ---
    rnd(ptrx, pln, NBUK * OUTD);
    gemm(pln, pwt + OFF_PROJ, pb, nullptr, pcnt, out, NBUK, CLAT, OUTD, 0);
}

// round 7
// speedup vs baseline: 3.7129x; 1.3459x over previous
#include <cuda_runtime.h>
#include <cuda_fp16.h>
#include <math.h>
#include <stdint.h>

#define NOBS 72000
#define NBUK 9000
#define LMAXX 8
#define DIM 256
#define NTOK 8
#define DH 32
#define DEPTH 8
#define FFND 1024
#define OUTD 2048
#define CLAT 512
#define NWELEM 7536640

// ---------------- scratch (device globals; no allocation allowed) ----------
static __device__ __align__(16) float  g_q  [NOBS * DIM];
static __device__ __align__(16) float  g_k  [NOBS * DIM];
static __device__ __align__(16) float  g_v  [NOBS * DIM];
static __device__ __align__(16) float  g_trx[NOBS * DIM];
static __device__ __align__(16) __half g_ah [NOBS * FFND];
static __device__ __align__(16) __half g_bh [NOBS * DIM];
static __device__ __align__(16) __half g_ch [NOBS * DIM];
static __device__ __align__(16) __half g_wh [NWELEM];
static __device__ int g_cnt[NBUK];
static __device__ int g_row[NOBS];

// offsets (elements) into transposed half weight slab [N,K]
#define OFF_MLPW 0
#define OFF_WQ   196608
#define OFF_WK   720896
#define OFF_WV   1245184
#define OFF_WO   1769472
#define OFF_W1   2293760
#define OFF_W2   4390912
#define OFF_PROJ 6488064

__device__ __forceinline__ float gelu_tanh(float x) {
    float x3 = x * x * x;
    float t = tanhf(0.7978845608028654f * (x + 0.044715f * x3));
    return 0.5f * x * (1.0f + t);
}

__device__ __forceinline__ void mma_fp16(float* c, const uint32_t* a,
                                         uint32_t b0, uint32_t b1) {
    asm volatile(
        "mma.sync.aligned.m16n8k16.row.col.f32.f16.f16.f32 "
        "{%0,%1,%2,%3},{%4,%5,%6,%7},{%8,%9},{%0,%1,%2,%3};\n"
        : "+f"(c[0]), "+f"(c[1]), "+f"(c[2]), "+f"(c[3])
        : "r"(a[0]), "r"(a[1]), "r"(a[2]), "r"(a[3]), "r"(b0), "r"(b1));
}

__device__ __forceinline__ void cp_async16(uint32_t saddr, const void* g, int srcB) {
    asm volatile("cp.async.cg.shared.global [%0], [%1], 16, %2;\n"
                 :: "r"(saddr), "l"(g), "r"(srcB));
}
__device__ __forceinline__ void cp_commit() {
    asm volatile("cp.async.commit_group;\n");
}
template <int N>
__device__ __forceinline__ void cp_wait() {
    asm volatile("cp.async.wait_group %0;\n" :: "n"(N));
}

// ---------------- FP16 tensor-core GEMM (m16n8k16), cp.async 3-stage --------
// C[M,N] = act(A[M,K] @ B[K,N] + bias) [+res] [gated]
// A: half [M,K] row-major. B: half TRANSPOSED [N,K] row-major.
// BM=128, BN=128, BK=32, 256 threads, 4(M)x2(N) warps (warp tile 32x64).
#define ASTR_B 80                   // padded row stride in bytes (32 halves + pad)
#define TILE_HB (128 * ASTR_B)      // 10240 B per operand tile
#define STAGE_HB (2 * TILE_HB)      // 20480 B per stage
#define GEMM_SMEM_H (3 * STAGE_HB)  // 61440 B

__global__ __launch_bounds__(256, 2)
void k_gemm_h(const __half* __restrict__ A, const __half* __restrict__ B,
              const float* __restrict__ bias, const float* __restrict__ res,
              const int* __restrict__ gate,
              float* __restrict__ Cf, __half* __restrict__ Ch,
              int M, int N, int K, int act)
{
    extern __shared__ char smem[];
    const uint32_t sb = (uint32_t)__cvta_generic_to_shared(smem);
    const int tid = threadIdx.x, lane = tid & 31, warp = tid >> 5;
    const int wm = warp & 3, wn = warp >> 2;
    const int rowBase = blockIdx.y << 7, colBase = blockIdx.x << 7;

    float acc[2][8][4];
#pragma unroll
    for (int i = 0; i < 2; i++)
#pragma unroll
        for (int j = 0; j < 8; j++)
#pragma unroll
            for (int l = 0; l < 4; l++) acc[i][j][l] = 0.0f;

    auto load_stage = [&](int t, int s) {
        uint32_t dst = sb + s * STAGE_HB;
        const int kt = t << 5;
#pragma unroll
        for (int r = 0; r < 2; r++) {        // A: 128 rows x 4 chunks of 16B
            int f = tid + (r << 8);
            int row = f >> 2, c = f & 3;
            int gm = rowBase + row;
            cp_async16(dst + row * ASTR_B + c * 16,
                       A + (size_t)(gm < M ? gm : 0) * K + kt + c * 8,
                       gm < M ? 16 : 0);
        }
#pragma unroll
        for (int r = 0; r < 2; r++) {        // B: 128 n-rows x 4 chunks
            int f = tid + (r << 8);
            int row = f >> 2, c = f & 3;
            cp_async16(dst + TILE_HB + row * ASTR_B + c * 16,
                       B + (size_t)(colBase + row) * K + kt + c * 8, 16);
        }
        cp_commit();
    };

    const int g = lane >> 2, t4 = lane & 3;

    auto compute = [&](int s) {
        const char* Ab = smem + s * STAGE_HB;
        const char* Bb = Ab + TILE_HB;
        const char* ap0 = Ab + (wm * 32 + g) * ASTR_B + t4 * 4;
        const char* bp0 = Bb + (wn * 64 + g) * ASTR_B + t4 * 4;
#pragma unroll
        for (int ks = 0; ks < 2; ks++) {
            uint32_t af[2][4];
#pragma unroll
            for (int mt = 0; mt < 2; mt++) {
                const char* ap = ap0 + ks * 32 + mt * 16 * ASTR_B;
                af[mt][0] = *(const uint32_t*)(ap);
                af[mt][1] = *(const uint32_t*)(ap + 8 * ASTR_B);
                af[mt][2] = *(const uint32_t*)(ap + 16);
                af[mt][3] = *(const uint32_t*)(ap + 8 * ASTR_B + 16);
            }
#pragma unroll
            for (int nt = 0; nt < 8; nt++) {
                const char* bp = bp0 + ks * 32 + nt * 8 * ASTR_B;
                uint32_t b0 = *(const uint32_t*)(bp);
                uint32_t b1 = *(const uint32_t*)(bp + 16);
                mma_fp16(acc[0][nt], af[0], b0, b1);
                mma_fp16(acc[1][nt], af[1], b0, b1);
            }
        }
    };

    const int T = K >> 5;
    load_stage(0, 0);
    load_stage(1, 1);
    for (int t = 0; t < T; t++) {
        cp_wait<1>();
        __syncthreads();
        if (t + 2 < T) load_stage(t + 2, (t + 2) % 3);
        compute(t % 3);
    }

    // ---------------- epilogue ----------------
#pragma unroll
    for (int mt = 0; mt < 2; mt++) {
#pragma unroll
        for (int hf = 0; hf < 2; hf++) {
            int gm = rowBase + wm * 32 + mt * 16 + (lane >> 2) + hf * 8;
            if (gm >= M) continue;
            bool gz = (gate && gate[gm] == 0);
#pragma unroll
            for (int nt = 0; nt < 8; nt++) {
                int gn = colBase + wn * 64 + nt * 8 + ((lane & 3) << 1);
                float cx = acc[mt][nt][hf * 2 + 0];
                float cy = acc[mt][nt][hf * 2 + 1];
                if (bias) {
                    float2 bv = *(const float2*)(bias + gn);
                    cx += bv.x; cy += bv.y;
                }
                if (act) { cx = gelu_tanh(cx); cy = gelu_tanh(cy); }
                if (res) {
                    float2 rv = *(const float2*)(res + (size_t)gm * N + gn);
                    cx += rv.x; cy += rv.y;
                }
                if (gz) { cx = 0.f; cy = 0.f; }
                if (Cf) {
                    *(float2*)(Cf + (size_t)gm * N + gn) = make_float2(cx, cy);
                } else {
                    *(__half2*)(Ch + (size_t)gm * N + gn) = __floats2half2_rn(cx, cy);
                }
            }
        }
    }
}

// ---------------- layernorm: outputs half (feeds GEMM A) --------------------
__global__ void k_ln(const float* __restrict__ X, __half* __restrict__ Y,
                     const float* __restrict__ G, const float* __restrict__ Bb)
{
    int row  = blockIdx.x * 8 + (threadIdx.x >> 5);
    int lane = threadIdx.x & 31;
    const float* x = X + (size_t)row * DIM;
    float v[8];
    float s = 0.f;
#pragma unroll
    for (int r = 0; r < 8; r++) { v[r] = x[lane + (r << 5)]; s += v[r]; }
#pragma unroll
    for (int off = 16; off; off >>= 1) s += __shfl_xor_sync(0xffffffffu, s, off);
    float mean = s * (1.0f / 256.0f);
    float vs = 0.f;
#pragma unroll
    for (int r = 0; r < 8; r++) { float d = v[r] - mean; vs = fmaf(d, d, vs); }
#pragma unroll
    for (int off = 16; off; off >>= 1) vs += __shfl_xor_sync(0xffffffffu, vs, off);
    float inv = rsqrtf(vs * (1.0f / 256.0f) + 1e-5f);
#pragma unroll
    for (int r = 0; r < 8; r++) {
        int c = lane + (r << 5);
        Y[(size_t)row * DIM + c] = __float2half((v[r] - mean) * inv * G[c] + Bb[c]);
    }
}

// ---------------- per-bucket cross attention (outputs half) -----------------
__global__ void k_attn(const float* __restrict__ Q, const float* __restrict__ Kx,
                       const float* __restrict__ V, __half* __restrict__ O)
{
    __shared__ __align__(16) float sQ[NTOK * DIM];
    __shared__ __align__(16) float sK[LMAXX * DIM];
    __shared__ __align__(16) float sV[LMAXX * DIM];
    int b = blockIdx.x;
    int tid = threadIdx.x;  // 64 threads
    const float4* q4 = (const float4*)(Q + (size_t)b * NTOK * DIM);
    const float4* k4 = (const float4*)(Kx + (size_t)b * LMAXX * DIM);
    const float4* v4 = (const float4*)(V + (size_t)b * LMAXX * DIM);
#pragma unroll
    for (int r = 0; r < 8; r++) {
        ((float4*)sQ)[tid + r * 64] = q4[tid + r * 64];
        ((float4*)sK)[tid + r * 64] = k4[tid + r * 64];
        ((float4*)sV)[tid + r * 64] = v4[tid + r * 64];
    }
    int cnt = g_cnt[b];
    __syncthreads();

    int h = tid >> 3, qi = tid & 7;
    const float* qp = sQ + qi * DIM + h * DH;
    float qr[DH];
#pragma unroll
    for (int d = 0; d < DH; d++) qr[d] = qp[d];

    float sc[LMAXX];
    float mx = -1e30f;
#pragma unroll
    for (int j = 0; j < LMAXX; j++) {
        const float* kp = sK + j * DIM + h * DH;
        float s = 0.f;
#pragma unroll
        for (int d = 0; d < DH; d++) s = fmaf(qr[d], kp[d], s);
        s = s * 0.17677669529663689f;
        if (j >= cnt) s -= 1e9f;
        sc[j] = s;
        mx = fmaxf(mx, s);
    }
    float den = 0.f;
#pragma unroll
    for (int j = 0; j < LMAXX; j++) { sc[j] = expf(sc[j] - mx); den += sc[j]; }
    float inv = 1.0f / den;
    float o[DH];
#pragma unroll
    for (int d = 0; d < DH; d++) o[d] = 0.f;
#pragma unroll
    for (int j = 0; j < LMAXX; j++) {
        float a = sc[j] * inv;
        const float* vp = sV + j * DIM + h * DH;
#pragma unroll
        for (int d = 0; d < DH; d++) o[d] = fmaf(a, vp[d], o[d]);
    }
    __half* op = O + (size_t)(b * NTOK + qi) * DIM + h * DH;
#pragma unroll
    for (int d = 0; d < DH; d++) op[d] = __float2half(o[d]);
}

// ---------------- dispatch helpers ------------------------------------------
__global__ void k_reset_cnt()
{
    int i = blockIdx.x * blockDim.x + threadIdx.x;
    if (i < NBUK) g_cnt[i] = 0;
}

__global__ void k_flatpos(const int* __restrict__ li)
{
    int i = blockIdx.x * blockDim.x + threadIdx.x;
    if (i >= NOBS) return;
    int d = li[3 * i], hh = li[3 * i + 1], w = li[3 * i + 2];
    int f = d * 1800 + hh * 60 + w;
    int pos = atomicAdd(&g_cnt[f], 1);
    g_row[i] = (pos < LMAXX) ? (f * LMAXX + pos) : -1;
}

__global__ void k_scatter(const __half* __restrict__ S)
{
    int wid  = (blockIdx.x * blockDim.x + threadIdx.x) >> 5;
    int lane = threadIdx.x & 31;
    if (wid >= NOBS) return;
    int dst = g_row[wid];
    if (dst < 0) return;
    ((uint4*)(g_ch + (size_t)dst * DIM))[lane] =
        ((const uint4*)(S + (size_t)wid * DIM))[lane];
}

__global__ void k_init_trx(const float* __restrict__ bg)
{
    int idx = blockIdx.x * blockDim.x + threadIdx.x;
    if (idx >= NOBS * DIM / 4) return;
    int row = idx >> 6;
    int t   = row & 7;
    int c4  = idx & 63;
    ((float4*)g_trx)[idx] = ((const float4*)bg)[t * 64 + c4];
}

// ---------------- fp32 -> half (activations) --------------------------------
__global__ void k_tohalf(const float4* __restrict__ s, __half* __restrict__ d, int n4)
{
    int i = blockIdx.x * blockDim.x + threadIdx.x;
    if (i >= n4) return;
    float4 v = s[i];
    ((__half2*)d)[2 * i]     = __floats2half2_rn(v.x, v.y);
    ((__half2*)d)[2 * i + 1] = __floats2half2_rn(v.z, v.w);
}

// ---------------- weight transpose+convert: W[K,N] fp32 -> WT[N,K] half -----
__global__ void k_wt(const float* __restrict__ W, __half* __restrict__ T,
                     int K, int N)
{
    __shared__ float tile[32][33];
    size_t boff = (size_t)blockIdx.z * K * N;
    int n0 = blockIdx.x * 32, k0 = blockIdx.y * 32;
#pragma unroll
    for (int r = 0; r < 4; r++) {
        int k = k0 + threadIdx.y + r * 8;
        tile[threadIdx.y + r * 8][threadIdx.x] =
            W[boff + (size_t)k * N + n0 + threadIdx.x];
    }
    __syncthreads();
#pragma unroll
    for (int r = 0; r < 4; r++) {
        int n = n0 + threadIdx.y + r * 8;
        T[boff + (size_t)n * K + k0 + threadIdx.x] =
            __float2half(tile[threadIdx.x][threadIdx.y + r * 8]);
    }
}

// ---------------- launch ------------------------------------------------------
extern "C" void kernel_launch(void* const* d_in, const int* in_sizes, int n_in,
                              void* d_out, int out_size)
{
    const float* x     = (const float*)d_in[0];
    const int*   li    = (const int*)  d_in[1];
    const float* mlp_w = (const float*)d_in[2];
    const float* mlp_b = (const float*)d_in[3];
    const float* bg    = (const float*)d_in[4];
    const float* ln1g  = (const float*)d_in[5];
    const float* ln1b  = (const float*)d_in[6];
    const float* wq    = (const float*)d_in[7];
    const float* bq    = (const float*)d_in[8];
    const float* wk    = (const float*)d_in[9];
    const float* bk    = (const float*)d_in[10];
    const float* wv    = (const float*)d_in[11];
    const float* bv    = (const float*)d_in[12];
    const float* wo    = (const float*)d_in[13];
    const float* bo    = (const float*)d_in[14];
    const float* ln2g  = (const float*)d_in[15];
    const float* ln2b  = (const float*)d_in[16];
    const float* w1    = (const float*)d_in[17];
    const float* b1    = (const float*)d_in[18];
    const float* w2    = (const float*)d_in[19];
    const float* b2    = (const float*)d_in[20];
    const float* pw    = (const float*)d_in[21];
    const float* pb    = (const float*)d_in[22];
    float* out = (float*)d_out;
    (void)in_sizes; (void)n_in; (void)out_size;

    float *pq, *pk, *pv, *ptrx;
    __half *pA, *pB, *pC, *pW;
    int *pcnt;
    cudaGetSymbolAddress((void**)&pq,   g_q);
    cudaGetSymbolAddress((void**)&pk,   g_k);
    cudaGetSymbolAddress((void**)&pv,   g_v);
    cudaGetSymbolAddress((void**)&ptrx, g_trx);
    cudaGetSymbolAddress((void**)&pA,   g_ah);
    cudaGetSymbolAddress((void**)&pB,   g_bh);
    cudaGetSymbolAddress((void**)&pC,   g_ch);
    cudaGetSymbolAddress((void**)&pW,   g_wh);
    cudaGetSymbolAddress((void**)&pcnt, g_cnt);

    cudaFuncSetAttribute(k_gemm_h, cudaFuncAttributeMaxDynamicSharedMemorySize,
                         GEMM_SMEM_H);

    // --- weight transpose+convert (deterministic, every call) ---
    dim3 wb(32, 8);
    k_wt<<<dim3(8, 8, 3),   wb>>>(mlp_w, pW + OFF_MLPW, 256, 256);
    k_wt<<<dim3(8, 8, 8),   wb>>>(wq,    pW + OFF_WQ,   256, 256);
    k_wt<<<dim3(8, 8, 8),   wb>>>(wk,    pW + OFF_WK,   256, 256);
    k_wt<<<dim3(8, 8, 8),   wb>>>(wv,    pW + OFF_WV,   256, 256);
    k_wt<<<dim3(8, 8, 8),   wb>>>(wo,    pW + OFF_WO,   256, 256);
    k_wt<<<dim3(32, 8, 8),  wb>>>(w1,    pW + OFF_W1,   256, 1024);
    k_wt<<<dim3(8, 32, 8),  wb>>>(w2,    pW + OFF_W2,   1024, 256);
    k_wt<<<dim3(16, 64, 1), wb>>>(pw,    pW + OFF_PROJ, 2048, 512);

    auto gemm = [&](const __half* A, int woff, const float* bias,
                    const float* res, const int* gate,
                    float* Cf, __half* Ch, int M, int N, int K, int act) {
        dim3 grid(N / 128, (M + 127) / 128);
        k_gemm_h<<<grid, 256, GEMM_SMEM_H>>>(A, pW + woff, bias, res, gate,
                                             Cf, Ch, M, N, K, act);
    };

    // --- obs feature MLP: fc1 -> gelu -> fc2 -> gelu -> fc3 ---
    k_tohalf<<<(NOBS * DIM / 4 + 255) / 256, 256>>>((const float4*)x, pB, NOBS * DIM / 4);
    gemm(pB, OFF_MLPW,             mlp_b,       nullptr, nullptr, nullptr, pA, NOBS, DIM, DIM, 1);
    gemm(pA, OFF_MLPW + 65536,     mlp_b + 256, nullptr, nullptr, nullptr, pB, NOBS, DIM, DIM, 1);
    gemm(pB, OFF_MLPW + 2 * 65536, mlp_b + 512, nullptr, nullptr, nullptr, pA, NOBS, DIM, DIM, 0);

    // --- dispatch into buckets ---
    k_reset_cnt<<<(NBUK + 255) / 256, 256>>>();
    k_flatpos<<<(NOBS + 255) / 256, 256>>>(li);
    k_scatter<<<NOBS / 8, 256>>>(pA);
    k_init_trx<<<NOBS * DIM / 4 / 256, 256>>>(bg);

    // --- 8-layer cross-attention transformer ---
    for (int l = 0; l < DEPTH; l++) {
        k_ln<<<NBUK, 256>>>(ptrx, pB, ln1g + l * DIM, ln1b + l * DIM);
        gemm(pB, OFF_WQ + l * 65536, bq + l * DIM, nullptr, nullptr, pq, nullptr, NOBS, DIM, DIM, 0);
        gemm(pC, OFF_WK + l * 65536, bk + l * DIM, nullptr, nullptr, pk, nullptr, NOBS, DIM, DIM, 0);
        gemm(pC, OFF_WV + l * 65536, bv + l * DIM, nullptr, nullptr, pv, nullptr, NOBS, DIM, DIM, 0);
        k_attn<<<NBUK, 64>>>(pq, pk, pv, pB);
        gemm(pB, OFF_WO + l * 65536, bo + l * DIM, ptrx, nullptr, ptrx, nullptr, NOBS, DIM, DIM, 0);
        k_ln<<<NBUK, 256>>>(ptrx, pB, ln2g + l * DIM, ln2b + l * DIM);
        gemm(pB, OFF_W1 + l * DIM * FFND, b1 + l * FFND, nullptr, nullptr, nullptr, pA, NOBS, FFND, DIM, 1);
        gemm(pA, OFF_W2 + l * FFND * DIM, b2 + l * DIM, ptrx, nullptr, ptrx, nullptr, NOBS, DIM, FFND, 0);
    }

    // --- final projection, gated by occupancy ---
    k_tohalf<<<(NBUK * OUTD / 4 + 255) / 256, 256>>>((const float4*)ptrx, pB, NBUK * OUTD / 4);
    gemm(pB, OFF_PROJ, pb, nullptr, pcnt, out, nullptr, NBUK, CLAT, OUTD, 0);
}

// round 8
// speedup vs baseline: 4.3513x; 1.1720x over previous
#include <cuda_runtime.h>
#include <cuda_fp16.h>
#include <math.h>
#include <stdint.h>

#define NOBS 72000
#define NBUK 9000
#define LMAXX 8
#define DIM 256
#define NTOK 8
#define DH 32
#define DEPTH 8
#define FFND 1024
#define OUTD 2048
#define CLAT 512
#define NWELEM 7536640

// ---------------- scratch (device globals; no allocation allowed) ----------
static __device__ __align__(16) float  g_q  [NOBS * DIM];
static __device__ __align__(16) float  g_k  [NOBS * DIM];
static __device__ __align__(16) float  g_v  [NOBS * DIM];
static __device__ __align__(16) float  g_trx[NOBS * DIM];
static __device__ __align__(16) __half g_ah [NOBS * FFND];
static __device__ __align__(16) __half g_bh [NOBS * DIM];
static __device__ __align__(16) __half g_ch [NOBS * DIM];
static __device__ __align__(16) __half g_wh [NWELEM];
static __device__ int g_cnt[NBUK];
static __device__ int g_row[NOBS];

// offsets (elements) into transposed half weight slab [N,K]
#define OFF_MLPW 0
#define OFF_WQ   196608
#define OFF_WK   720896
#define OFF_WV   1245184
#define OFF_WO   1769472
#define OFF_W1   2293760
#define OFF_W2   4390912
#define OFF_PROJ 6488064

__device__ __forceinline__ float gelu_tanh(float x) {
    float x3 = x * x * x;
    float t = tanhf(0.7978845608028654f * (x + 0.044715f * x3));
    return 0.5f * x * (1.0f + t);
}

__device__ __forceinline__ void mma_fp16(float* c, const uint32_t* a,
                                         uint32_t b0, uint32_t b1) {
    asm volatile(
        "mma.sync.aligned.m16n8k16.row.col.f32.f16.f16.f32 "
        "{%0,%1,%2,%3},{%4,%5,%6,%7},{%8,%9},{%0,%1,%2,%3};\n"
        : "+f"(c[0]), "+f"(c[1]), "+f"(c[2]), "+f"(c[3])
        : "r"(a[0]), "r"(a[1]), "r"(a[2]), "r"(a[3]), "r"(b0), "r"(b1));
}

__device__ __forceinline__ void ldsm_x4(uint32_t& r0, uint32_t& r1,
                                        uint32_t& r2, uint32_t& r3, uint32_t a) {
    asm volatile("ldmatrix.sync.aligned.m8n8.x4.shared.b16 {%0,%1,%2,%3}, [%4];"
                 : "=r"(r0), "=r"(r1), "=r"(r2), "=r"(r3) : "r"(a));
}

__device__ __forceinline__ void cp_async16(uint32_t saddr, const void* g, int srcB) {
    asm volatile("cp.async.cg.shared.global [%0], [%1], 16, %2;\n"
                 :: "r"(saddr), "l"(g), "r"(srcB));
}
__device__ __forceinline__ void cp_commit() {
    asm volatile("cp.async.commit_group;\n");
}
template <int N>
__device__ __forceinline__ void cp_wait() {
    asm volatile("cp.async.wait_group %0;\n" :: "n"(N));
}

// ---------------- FP16 tensor-core GEMM (ldmatrix + m16n8k16) ---------------
// C[M,N] = act(A[M,K] @ B[K,N] + bias) [+res] [gated]
// A: half [M,K] row-major. B: half TRANSPOSED [N,K] row-major.
// BM=128, BN=128, BK=64, 256 thr, 4(M)x2(N) warps, 3-stage cp.async.
#define ASTR_B 144                  // padded row stride: 128B data + 16B pad
#define TILE_HB (128 * ASTR_B)      // 18432 B per operand tile
#define STAGE_HB (2 * TILE_HB)      // 36864 B per stage
#define GEMM_SMEM_H (3 * STAGE_HB)  // 110592 B

__global__ __launch_bounds__(256, 2)
void k_gemm_h(const __half* __restrict__ A, const __half* __restrict__ B,
              const float* __restrict__ bias, const float* __restrict__ res,
              const int* __restrict__ gate,
              float* __restrict__ Cf, __half* __restrict__ Ch,
              int M, int N, int K, int act)
{
    extern __shared__ char smem[];
    const uint32_t sb = (uint32_t)__cvta_generic_to_shared(smem);
    const int tid = threadIdx.x, lane = tid & 31, warp = tid >> 5;
    const int wm = warp & 3, wn = warp >> 2;
    const int rowBase = blockIdx.y << 7, colBase = blockIdx.x << 7;

    float acc[2][8][4];
#pragma unroll
    for (int i = 0; i < 2; i++)
#pragma unroll
        for (int j = 0; j < 8; j++)
#pragma unroll
            for (int l = 0; l < 4; l++) acc[i][j][l] = 0.0f;

    auto load_stage = [&](int t, int s) {
        uint32_t dst = sb + s * STAGE_HB;
        const int kt = t << 6;
#pragma unroll
        for (int r = 0; r < 4; r++) {        // A: 128 rows x 8 chunks of 16B
            int f = tid + (r << 8);
            int row = f >> 3, c = f & 7;
            int gm = rowBase + row;
            cp_async16(dst + row * ASTR_B + c * 16,
                       A + (size_t)(gm < M ? gm : 0) * K + kt + c * 8,
                       gm < M ? 16 : 0);
        }
#pragma unroll
        for (int r = 0; r < 4; r++) {        // B: 128 n-rows x 8 chunks
            int f = tid + (r << 8);
            int row = f >> 3, c = f & 7;
            cp_async16(dst + TILE_HB + row * ASTR_B + c * 16,
                       B + (size_t)(colBase + row) * K + kt + c * 8, 16);
        }
        cp_commit();
    };

    // per-lane ldmatrix base addresses (j = lane/8 selects the 8x8 matrix)
    const int li = lane & 7, lj = lane >> 3;
    // A x4: mats [m0-7,k0-7],[m8-15,k0-7],[m0-7,k8-15],[m8-15,k8-15]
    const uint32_t aoff = (uint32_t)((wm * 32 + (lj & 1) * 8 + li) * ASTR_B
                                     + (lj >> 1) * 16);
    // B x4: mats [n0-7,k0-7],[n0-7,k8-15],[n8-15,k0-7],[n8-15,k8-15]
    const uint32_t boff = (uint32_t)(TILE_HB + (wn * 64 + (lj >> 1) * 8 + li) * ASTR_B
                                     + (lj & 1) * 16);

    auto compute = [&](int s) {
        const uint32_t st = sb + s * STAGE_HB;
#pragma unroll
        for (int ks = 0; ks < 4; ks++) {      // 4 x k16
            uint32_t af[2][4];
            ldsm_x4(af[0][0], af[0][1], af[0][2], af[0][3], st + aoff + ks * 32);
            ldsm_x4(af[1][0], af[1][1], af[1][2], af[1][3],
                    st + aoff + 16 * ASTR_B + ks * 32);
#pragma unroll
            for (int g16 = 0; g16 < 4; g16++) {
                uint32_t b0, b1, b2, b3;
                ldsm_x4(b0, b1, b2, b3, st + boff + g16 * (16 * ASTR_B) + ks * 32);
                mma_fp16(acc[0][g16 * 2 + 0], af[0], b0, b1);
                mma_fp16(acc[1][g16 * 2 + 0], af[1], b0, b1);
                mma_fp16(acc[0][g16 * 2 + 1], af[0], b2, b3);
                mma_fp16(acc[1][g16 * 2 + 1], af[1], b2, b3);
            }
        }
    };

    const int T = K >> 6;
    load_stage(0, 0);
    if (T > 1) load_stage(1, 1);
    for (int t = 0; t < T; t++) {
        if (t + 1 < T) cp_wait<1>(); else cp_wait<0>();
        __syncthreads();
        if (t + 2 < T) load_stage(t + 2, (t + 2) % 3);
        compute(t % 3);
    }

    // ---------------- epilogue ----------------
#pragma unroll
    for (int mt = 0; mt < 2; mt++) {
#pragma unroll
        for (int hf = 0; hf < 2; hf++) {
            int gm = rowBase + wm * 32 + mt * 16 + (lane >> 2) + hf * 8;
            if (gm >= M) continue;
            bool gz = (gate && gate[gm] == 0);
#pragma unroll
            for (int nt = 0; nt < 8; nt++) {
                int gn = colBase + wn * 64 + nt * 8 + ((lane & 3) << 1);
                float cx = acc[mt][nt][hf * 2 + 0];
                float cy = acc[mt][nt][hf * 2 + 1];
                if (bias) {
                    float2 bv = *(const float2*)(bias + gn);
                    cx += bv.x; cy += bv.y;
                }
                if (act) { cx = gelu_tanh(cx); cy = gelu_tanh(cy); }
                if (res) {
                    float2 rv = *(const float2*)(res + (size_t)gm * N + gn);
                    cx += rv.x; cy += rv.y;
                }
                if (gz) { cx = 0.f; cy = 0.f; }
                if (Cf) {
                    *(float2*)(Cf + (size_t)gm * N + gn) = make_float2(cx, cy);
                } else {
                    *(__half2*)(Ch + (size_t)gm * N + gn) = __floats2half2_rn(cx, cy);
                }
            }
        }
    }
}

// ---------------- layernorm: outputs half (feeds GEMM A) --------------------
__global__ void k_ln(const float* __restrict__ X, __half* __restrict__ Y,
                     const float* __restrict__ G, const float* __restrict__ Bb)
{
    int row  = blockIdx.x * 8 + (threadIdx.x >> 5);
    int lane = threadIdx.x & 31;
    const float* x = X + (size_t)row * DIM;
    float v[8];
    float s = 0.f;
#pragma unroll
    for (int r = 0; r < 8; r++) { v[r] = x[lane + (r << 5)]; s += v[r]; }
#pragma unroll
    for (int off = 16; off; off >>= 1) s += __shfl_xor_sync(0xffffffffu, s, off);
    float mean = s * (1.0f / 256.0f);
    float vs = 0.f;
#pragma unroll
    for (int r = 0; r < 8; r++) { float d = v[r] - mean; vs = fmaf(d, d, vs); }
#pragma unroll
    for (int off = 16; off; off >>= 1) vs += __shfl_xor_sync(0xffffffffu, vs, off);
    float inv = rsqrtf(vs * (1.0f / 256.0f) + 1e-5f);
#pragma unroll
    for (int r = 0; r < 8; r++) {
        int c = lane + (r << 5);
        Y[(size_t)row * DIM + c] = __float2half((v[r] - mean) * inv * G[c] + Bb[c]);
    }
}

// ---------------- per-bucket cross attention (outputs half) -----------------
__global__ void k_attn(const float* __restrict__ Q, const float* __restrict__ Kx,
                       const float* __restrict__ V, __half* __restrict__ O)
{
    __shared__ __align__(16) float sQ[NTOK * DIM];
    __shared__ __align__(16) float sK[LMAXX * DIM];
    __shared__ __align__(16) float sV[LMAXX * DIM];
    int b = blockIdx.x;
    int tid = threadIdx.x;  // 64 threads
    const float4* q4 = (const float4*)(Q + (size_t)b * NTOK * DIM);
    const float4* k4 = (const float4*)(Kx + (size_t)b * LMAXX * DIM);
    const float4* v4 = (const float4*)(V + (size_t)b * LMAXX * DIM);
#pragma unroll
    for (int r = 0; r < 8; r++) {
        ((float4*)sQ)[tid + r * 64] = q4[tid + r * 64];
        ((float4*)sK)[tid + r * 64] = k4[tid + r * 64];
        ((float4*)sV)[tid + r * 64] = v4[tid + r * 64];
    }
    int cnt = g_cnt[b];
    __syncthreads();

    int h = tid >> 3, qi = tid & 7;
    const float* qp = sQ + qi * DIM + h * DH;
    float qr[DH];
#pragma unroll
    for (int d = 0; d < DH; d++) qr[d] = qp[d];

    float sc[LMAXX];
    float mx = -1e30f;
#pragma unroll
    for (int j = 0; j < LMAXX; j++) {
        const float* kp = sK + j * DIM + h * DH;
        float s = 0.f;
#pragma unroll
        for (int d = 0; d < DH; d++) s = fmaf(qr[d], kp[d], s);
        s = s * 0.17677669529663689f;
        if (j >= cnt) s -= 1e9f;
        sc[j] = s;
        mx = fmaxf(mx, s);
    }
    float den = 0.f;
#pragma unroll
    for (int j = 0; j < LMAXX; j++) { sc[j] = expf(sc[j] - mx); den += sc[j]; }
    float inv = 1.0f / den;
    float o[DH];
#pragma unroll
    for (int d = 0; d < DH; d++) o[d] = 0.f;
#pragma unroll
    for (int j = 0; j < LMAXX; j++) {
        float a = sc[j] * inv;
        const float* vp = sV + j * DIM + h * DH;
#pragma unroll
        for (int d = 0; d < DH; d++) o[d] = fmaf(a, vp[d], o[d]);
    }
    __half* op = O + (size_t)(b * NTOK + qi) * DIM + h * DH;
#pragma unroll
    for (int d = 0; d < DH; d++) op[d] = __float2half(o[d]);
}

// ---------------- dispatch helpers ------------------------------------------
__global__ void k_reset_cnt()
{
    int i = blockIdx.x * blockDim.x + threadIdx.x;
    if (i < NBUK) g_cnt[i] = 0;
}

__global__ void k_flatpos(const int* __restrict__ li)
{
    int i = blockIdx.x * blockDim.x + threadIdx.x;
    if (i >= NOBS) return;
    int d = li[3 * i], hh = li[3 * i + 1], w = li[3 * i + 2];
    int f = d * 1800 + hh * 60 + w;
    int pos = atomicAdd(&g_cnt[f], 1);
    g_row[i] = (pos < LMAXX) ? (f * LMAXX + pos) : -1;
}

__global__ void k_scatter(const __half* __restrict__ S)
{
    int wid  = (blockIdx.x * blockDim.x + threadIdx.x) >> 5;
    int lane = threadIdx.x & 31;
    if (wid >= NOBS) return;
    int dst = g_row[wid];
    if (dst < 0) return;
    ((uint4*)(g_ch + (size_t)dst * DIM))[lane] =
        ((const uint4*)(S + (size_t)wid * DIM))[lane];
}

__global__ void k_init_trx(const float* __restrict__ bg)
{
    int idx = blockIdx.x * blockDim.x + threadIdx.x;
    if (idx >= NOBS * DIM / 4) return;
    int row = idx >> 6;
    int t   = row & 7;
    int c4  = idx & 63;
    ((float4*)g_trx)[idx] = ((const float4*)bg)[t * 64 + c4];
}

// ---------------- fp32 -> half (activations) --------------------------------
__global__ void k_tohalf(const float4* __restrict__ s, __half* __restrict__ d, int n4)
{
    int i = blockIdx.x * blockDim.x + threadIdx.x;
    if (i >= n4) return;
    float4 v = s[i];
    ((__half2*)d)[2 * i]     = __floats2half2_rn(v.x, v.y);
    ((__half2*)d)[2 * i + 1] = __floats2half2_rn(v.z, v.w);
}

// ---------------- weight transpose+convert: W[K,N] fp32 -> WT[N,K] half -----
__global__ void k_wt(const float* __restrict__ W, __half* __restrict__ T,
                     int K, int N)
{
    __shared__ float tile[32][33];
    size_t boff = (size_t)blockIdx.z * K * N;
    int n0 = blockIdx.x * 32, k0 = blockIdx.y * 32;
#pragma unroll
    for (int r = 0; r < 4; r++) {
        int k = k0 + threadIdx.y + r * 8;
        tile[threadIdx.y + r * 8][threadIdx.x] =
            W[boff + (size_t)k * N + n0 + threadIdx.x];
    }
    __syncthreads();
#pragma unroll
    for (int r = 0; r < 4; r++) {
        int n = n0 + threadIdx.y + r * 8;
        T[boff + (size_t)n * K + k0 + threadIdx.x] =
            __float2half(tile[threadIdx.x][threadIdx.y + r * 8]);
    }
}

// ---------------- launch ------------------------------------------------------
extern "C" void kernel_launch(void* const* d_in, const int* in_sizes, int n_in,
                              void* d_out, int out_size)
{
    const float* x     = (const float*)d_in[0];
    const int*   li    = (const int*)  d_in[1];
    const float* mlp_w = (const float*)d_in[2];
    const float* mlp_b = (const float*)d_in[3];
    const float* bg    = (const float*)d_in[4];
    const float* ln1g  = (const float*)d_in[5];
    const float* ln1b  = (const float*)d_in[6];
    const float* wq    = (const float*)d_in[7];
    const float* bq    = (const float*)d_in[8];
    const float* wk    = (const float*)d_in[9];
    const float* bk    = (const float*)d_in[10];
    const float* wv    = (const float*)d_in[11];
    const float* bv    = (const float*)d_in[12];
    const float* wo    = (const float*)d_in[13];
    const float* bo    = (const float*)d_in[14];
    const float* ln2g  = (const float*)d_in[15];
    const float* ln2b  = (const float*)d_in[16];
    const float* w1    = (const float*)d_in[17];
    const float* b1    = (const float*)d_in[18];
    const float* w2    = (const float*)d_in[19];
    const float* b2    = (const float*)d_in[20];
    const float* pw    = (const float*)d_in[21];
    const float* pb    = (const float*)d_in[22];
    float* out = (float*)d_out;
    (void)in_sizes; (void)n_in; (void)out_size;

    float *pq, *pk, *pv, *ptrx;
    __half *pA, *pB, *pC, *pW;
    int *pcnt;
    cudaGetSymbolAddress((void**)&pq,   g_q);
    cudaGetSymbolAddress((void**)&pk,   g_k);
    cudaGetSymbolAddress((void**)&pv,   g_v);
    cudaGetSymbolAddress((void**)&ptrx, g_trx);
    cudaGetSymbolAddress((void**)&pA,   g_ah);
    cudaGetSymbolAddress((void**)&pB,   g_bh);
    cudaGetSymbolAddress((void**)&pC,   g_ch);
    cudaGetSymbolAddress((void**)&pW,   g_wh);
    cudaGetSymbolAddress((void**)&pcnt, g_cnt);

    cudaFuncSetAttribute(k_gemm_h, cudaFuncAttributeMaxDynamicSharedMemorySize,
                         GEMM_SMEM_H);

    // --- weight transpose+convert (deterministic, every call) ---
    dim3 wb(32, 8);
    k_wt<<<dim3(8, 8, 3),   wb>>>(mlp_w, pW + OFF_MLPW, 256, 256);
    k_wt<<<dim3(8, 8, 8),   wb>>>(wq,    pW + OFF_WQ,   256, 256);
    k_wt<<<dim3(8, 8, 8),   wb>>>(wk,    pW + OFF_WK,   256, 256);
    k_wt<<<dim3(8, 8, 8),   wb>>>(wv,    pW + OFF_WV,   256, 256);
    k_wt<<<dim3(8, 8, 8),   wb>>>(wo,    pW + OFF_WO,   256, 256);
    k_wt<<<dim3(32, 8, 8),  wb>>>(w1,    pW + OFF_W1,   256, 1024);
    k_wt<<<dim3(8, 32, 8),  wb>>>(w2,    pW + OFF_W2,   1024, 256);
    k_wt<<<dim3(16, 64, 1), wb>>>(pw,    pW + OFF_PROJ, 2048, 512);

    auto gemm = [&](const __half* A, int woff, const float* bias,
                    const float* res, const int* gate,
                    float* Cf, __half* Ch, int M, int N, int K, int act) {
        dim3 grid(N / 128, (M + 127) / 128);
        k_gemm_h<<<grid, 256, GEMM_SMEM_H>>>(A, pW + woff, bias, res, gate,
                                             Cf, Ch, M, N, K, act);
    };

    // --- obs feature MLP: fc1 -> gelu -> fc2 -> gelu -> fc3 ---
    k_tohalf<<<(NOBS * DIM / 4 + 255) / 256, 256>>>((const float4*)x, pB, NOBS * DIM / 4);
    gemm(pB, OFF_MLPW,             mlp_b,       nullptr, nullptr, nullptr, pA, NOBS, DIM, DIM, 1);
    gemm(pA, OFF_MLPW + 65536,     mlp_b + 256, nullptr, nullptr, nullptr, pB, NOBS, DIM, DIM, 1);
    gemm(pB, OFF_MLPW + 2 * 65536, mlp_b + 512, nullptr, nullptr, nullptr, pA, NOBS, DIM, DIM, 0);

    // --- dispatch into buckets ---
    k_reset_cnt<<<(NBUK + 255) / 256, 256>>>();
    k_flatpos<<<(NOBS + 255) / 256, 256>>>(li);
    k_scatter<<<NOBS / 8, 256>>>(pA);
    k_init_trx<<<NOBS * DIM / 4 / 256, 256>>>(bg);

    // --- 8-layer cross-attention transformer ---
    for (int l = 0; l < DEPTH; l++) {
        k_ln<<<NBUK, 256>>>(ptrx, pB, ln1g + l * DIM, ln1b + l * DIM);
        gemm(pB, OFF_WQ + l * 65536, bq + l * DIM, nullptr, nullptr, pq, nullptr, NOBS, DIM, DIM, 0);
        gemm(pC, OFF_WK + l * 65536, bk + l * DIM, nullptr, nullptr, pk, nullptr, NOBS, DIM, DIM, 0);
        gemm(pC, OFF_WV + l * 65536, bv + l * DIM, nullptr, nullptr, pv, nullptr, NOBS, DIM, DIM, 0);
        k_attn<<<NBUK, 64>>>(pq, pk, pv, pB);
        gemm(pB, OFF_WO + l * 65536, bo + l * DIM, ptrx, nullptr, ptrx, nullptr, NOBS, DIM, DIM, 0);
        k_ln<<<NBUK, 256>>>(ptrx, pB, ln2g + l * DIM, ln2b + l * DIM);
        gemm(pB, OFF_W1 + l * DIM * FFND, b1 + l * FFND, nullptr, nullptr, nullptr, pA, NOBS, FFND, DIM, 1);
        gemm(pA, OFF_W2 + l * FFND * DIM, b2 + l * DIM, ptrx, nullptr, ptrx, nullptr, NOBS, DIM, FFND, 0);
    }

    // --- final projection, gated by occupancy ---
    k_tohalf<<<(NBUK * OUTD / 4 + 255) / 256, 256>>>((const float4*)ptrx, pB, NBUK * OUTD / 4);
    gemm(pB, OFF_PROJ, pb, nullptr, pcnt, out, nullptr, NBUK, CLAT, OUTD, 0);
}

// round 12
// speedup vs baseline: 5.1081x; 1.1739x over previous
#include <cuda_runtime.h>
#include <cuda_fp16.h>
#include <math.h>
#include <stdint.h>

#define NOBS 72000
#define NBUK 9000
#define LMAXX 8
#define DIM 256
#define NTOK 8
#define DH 32
#define DEPTH 8
#define FFND 1024
#define OUTD 2048
#define CLAT 512
#define NWELEM 7536640

// ---------------- scratch (device globals; no allocation allowed) ----------
static __device__ __align__(16) float  g_trx[NOBS * DIM];
static __device__ __align__(16) __half g_ah [NOBS * FFND];
static __device__ __align__(16) __half g_bh [NOBS * DIM];
static __device__ __align__(16) __half g_ch [NOBS * DIM];
static __device__ __align__(16) __half g_kh [NOBS * DIM * DEPTH];
static __device__ __align__(16) __half g_vh [NOBS * DIM * DEPTH];
static __device__ __align__(16) __half g_wh [NWELEM];
static __device__ int g_cnt[NBUK];
static __device__ int g_row[NOBS];

// offsets (elements) into transposed half weight slab [N,K]
#define OFF_MLPW 0
#define OFF_WQ   196608
#define OFF_WK   720896
#define OFF_WV   1245184
#define OFF_WO   1769472
#define OFF_W1   2293760
#define OFF_W2   4390912
#define OFF_PROJ 6488064

__device__ __forceinline__ float gelu_tanh(float x) {
    float x3 = x * x * x;
    float t = tanhf(0.7978845608028654f * (x + 0.044715f * x3));
    return 0.5f * x * (1.0f + t);
}

__device__ __forceinline__ void mma_fp16(float* c, const uint32_t* a,
                                         uint32_t b0, uint32_t b1) {
    asm volatile(
        "mma.sync.aligned.m16n8k16.row.col.f32.f16.f16.f32 "
        "{%0,%1,%2,%3},{%4,%5,%6,%7},{%8,%9},{%0,%1,%2,%3};\n"
        : "+f"(c[0]), "+f"(c[1]), "+f"(c[2]), "+f"(c[3])
        : "r"(a[0]), "r"(a[1]), "r"(a[2]), "r"(a[3]), "r"(b0), "r"(b1));
}

__device__ __forceinline__ void ldsm_x4(uint32_t& r0, uint32_t& r1,
                                        uint32_t& r2, uint32_t& r3, uint32_t a) {
    asm volatile("ldmatrix.sync.aligned.m8n8.x4.shared.b16 {%0,%1,%2,%3}, [%4];"
                 : "=r"(r0), "=r"(r1), "=r"(r2), "=r"(r3) : "r"(a));
}

__device__ __forceinline__ void cp_async16(uint32_t saddr, const void* g, int srcB) {
    asm volatile("cp.async.cg.shared.global [%0], [%1], 16, %2;\n"
                 :: "r"(saddr), "l"(g), "r"(srcB));
}
__device__ __forceinline__ void cp_commit() {
    asm volatile("cp.async.commit_group;\n");
}
template <int N>
__device__ __forceinline__ void cp_wait() {
    asm volatile("cp.async.wait_group %0;\n" :: "n"(N));
}

// ---------------- FP16 tensor-core GEMM (ldmatrix + m16n8k16) ---------------
// C[M,N] = act(A[M,K] @ B[K,N] + bias) [+res] [gated]
// A: half [M,K] row-major. B: half TRANSPOSED [N,K] row-major.
// BM=128, BN=128, BK=64, 256 thr, 4(M)x2(N) warps, 3-stage cp.async.
#define ASTR_B 144                  // padded row stride: 128B data + 16B pad
#define TILE_HB (128 * ASTR_B)      // 18432 B per operand tile
#define STAGE_HB (2 * TILE_HB)      // 36864 B per stage
#define GEMM_SMEM_H (3 * STAGE_HB)  // 110592 B

__global__ __launch_bounds__(256, 2)
void k_gemm_h(const __half* __restrict__ A, const __half* __restrict__ B,
              const float* __restrict__ bias, const float* __restrict__ res,
              const int* __restrict__ gate,
              float* __restrict__ Cf, __half* __restrict__ Ch,
              int M, int N, int K, int act)
{
    extern __shared__ char smem[];
    const uint32_t sb = (uint32_t)__cvta_generic_to_shared(smem);
    const int tid = threadIdx.x, lane = tid & 31, warp = tid >> 5;
    const int wm = warp & 3, wn = warp >> 2;
    const int rowBase = blockIdx.y << 7, colBase = blockIdx.x << 7;

    float acc[2][8][4];
#pragma unroll
    for (int i = 0; i < 2; i++)
#pragma unroll
        for (int j = 0; j < 8; j++)
#pragma unroll
            for (int l = 0; l < 4; l++) acc[i][j][l] = 0.0f;

    auto load_stage = [&](int t, int s) {
        uint32_t dst = sb + s * STAGE_HB;
        const int kt = t << 6;
#pragma unroll
        for (int r = 0; r < 4; r++) {        // A: 128 rows x 8 chunks of 16B
            int f = tid + (r << 8);
            int row = f >> 3, c = f & 7;
            int gm = rowBase + row;
            cp_async16(dst + row * ASTR_B + c * 16,
                       A + (size_t)(gm < M ? gm : 0) * K + kt + c * 8,
                       gm < M ? 16 : 0);
        }
#pragma unroll
        for (int r = 0; r < 4; r++) {        // B: 128 n-rows x 8 chunks
            int f = tid + (r << 8);
            int row = f >> 3, c = f & 7;
            cp_async16(dst + TILE_HB + row * ASTR_B + c * 16,
                       B + (size_t)(colBase + row) * K + kt + c * 8, 16);
        }
        cp_commit();
    };

    const int li = lane & 7, lj = lane >> 3;
    const uint32_t aoff = (uint32_t)((wm * 32 + (lj & 1) * 8 + li) * ASTR_B
                                     + (lj >> 1) * 16);
    const uint32_t boff = (uint32_t)(TILE_HB + (wn * 64 + (lj >> 1) * 8 + li) * ASTR_B
                                     + (lj & 1) * 16);

    auto compute = [&](int s) {
        const uint32_t st = sb + s * STAGE_HB;
#pragma unroll
        for (int ks = 0; ks < 4; ks++) {      // 4 x k16
            uint32_t af[2][4];
            ldsm_x4(af[0][0], af[0][1], af[0][2], af[0][3], st + aoff + ks * 32);
            ldsm_x4(af[1][0], af[1][1], af[1][2], af[1][3],
                    st + aoff + 16 * ASTR_B + ks * 32);
#pragma unroll
            for (int g16 = 0; g16 < 4; g16++) {
                uint32_t b0, b1, b2, b3;
                ldsm_x4(b0, b1, b2, b3, st + boff + g16 * (16 * ASTR_B) + ks * 32);
                mma_fp16(acc[0][g16 * 2 + 0], af[0], b0, b1);
                mma_fp16(acc[1][g16 * 2 + 0], af[1], b0, b1);
                mma_fp16(acc[0][g16 * 2 + 1], af[0], b2, b3);
                mma_fp16(acc[1][g16 * 2 + 1], af[1], b2, b3);
            }
        }
    };

    const int T = K >> 6;
    load_stage(0, 0);
    if (T > 1) load_stage(1, 1);
    for (int t = 0; t < T; t++) {
        if (t + 1 < T) cp_wait<1>(); else cp_wait<0>();
        __syncthreads();
        if (t + 2 < T) load_stage(t + 2, (t + 2) % 3);
        compute(t % 3);
    }

    // ---------------- epilogue ----------------
#pragma unroll
    for (int mt = 0; mt < 2; mt++) {
#pragma unroll
        for (int hf = 0; hf < 2; hf++) {
            int gm = rowBase + wm * 32 + mt * 16 + (lane >> 2) + hf * 8;
            if (gm >= M) continue;
            bool gz = (gate && gate[gm] == 0);
#pragma unroll
            for (int nt = 0; nt < 8; nt++) {
                int gn = colBase + wn * 64 + nt * 8 + ((lane & 3) << 1);
                float cx = acc[mt][nt][hf * 2 + 0];
                float cy = acc[mt][nt][hf * 2 + 1];
                if (bias) {
                    float2 bv = *(const float2*)(bias + gn);
                    cx += bv.x; cy += bv.y;
                }
                if (act) { cx = gelu_tanh(cx); cy = gelu_tanh(cy); }
                if (res) {
                    float2 rv = *(const float2*)(res + (size_t)gm * N + gn);
                    cx += rv.x; cy += rv.y;
                }
                if (gz) { cx = 0.f; cy = 0.f; }
                if (Cf)
                    *(float2*)(Cf + (size_t)gm * N + gn) = make_float2(cx, cy);
                if (Ch)
                    *(__half2*)(Ch + (size_t)gm * N + gn) = __floats2half2_rn(cx, cy);
            }
        }
    }
}

// ---------------- layernorm: outputs half (feeds GEMM A) --------------------
__global__ void k_ln(const float* __restrict__ X, __half* __restrict__ Y,
                     const float* __restrict__ G, const float* __restrict__ Bb)
{
    int row  = blockIdx.x * 8 + (threadIdx.x >> 5);
    int lane = threadIdx.x & 31;
    const float* x = X + (size_t)row * DIM;
    float v[8];
    float s = 0.f;
#pragma unroll
    for (int r = 0; r < 8; r++) { v[r] = x[lane + (r << 5)]; s += v[r]; }
#pragma unroll
    for (int off = 16; off; off >>= 1) s += __shfl_xor_sync(0xffffffffu, s, off);
    float mean = s * (1.0f / 256.0f);
    float vs = 0.f;
#pragma unroll
    for (int r = 0; r < 8; r++) { float d = v[r] - mean; vs = fmaf(d, d, vs); }
#pragma unroll
    for (int off = 16; off; off >>= 1) vs += __shfl_xor_sync(0xffffffffu, vs, off);
    float inv = rsqrtf(vs * (1.0f / 256.0f) + 1e-5f);
#pragma unroll
    for (int r = 0; r < 8; r++) {
        int c = lane + (r << 5);
        Y[(size_t)row * DIM + c] = __float2half((v[r] - mean) * inv * G[c] + Bb[c]);
    }
}

// ---------------- per-bucket cross attention (half in / half out) -----------
// K/V rows have stride DIM*DEPTH; loff = layer * DIM selects the layer slice.
__global__ void k_attn(const __half* __restrict__ Q, const __half* __restrict__ Kx,
                       const __half* __restrict__ V, __half* __restrict__ O,
                       int loff)
{
    __shared__ __align__(16) __half sQ[NTOK * DIM];
    __shared__ __align__(16) __half sK[LMAXX * DIM];
    __shared__ __align__(16) __half sV[LMAXX * DIM];
    int b = blockIdx.x;
    int tid = threadIdx.x;  // 64 threads
#pragma unroll
    for (int r = 0; r < 4; r++) {
        int idx = tid + r * 64;          // 0..255 uint4 slots
        int row = idx >> 5, c8 = idx & 31;
        ((uint4*)sQ)[idx] = *(const uint4*)(Q + (size_t)(b * 8 + row) * DIM + c8 * 8);
        ((uint4*)sK)[idx] = *(const uint4*)(Kx + (size_t)(b * 8 + row) * (DIM * DEPTH)
                                            + loff + c8 * 8);
        ((uint4*)sV)[idx] = *(const uint4*)(V + (size_t)(b * 8 + row) * (DIM * DEPTH)
                                            + loff + c8 * 8);
    }
    int cnt = g_cnt[b];
    __syncthreads();

    int h = tid >> 3, qi = tid & 7;
    const __half2* qp = (const __half2*)(sQ + qi * DIM + h * DH);
    float2 qr[DH / 2];
#pragma unroll
    for (int d = 0; d < DH / 2; d++) qr[d] = __half22float2(qp[d]);

    float sc[LMAXX];
    float mx = -1e30f;
#pragma unroll
    for (int j = 0; j < LMAXX; j++) {
        const __half2* kp = (const __half2*)(sK + j * DIM + h * DH);
        float s = 0.f;
#pragma unroll
        for (int d = 0; d < DH / 2; d++) {
            float2 kv = __half22float2(kp[d]);
            s = fmaf(qr[d].x, kv.x, s);
            s = fmaf(qr[d].y, kv.y, s);
        }
        s = s * 0.17677669529663689f;
        if (j >= cnt) s -= 1e9f;
        sc[j] = s;
        mx = fmaxf(mx, s);
    }
    float den = 0.f;
#pragma unroll
    for (int j = 0; j < LMAXX; j++) { sc[j] = expf(sc[j] - mx); den += sc[j]; }
    float inv = 1.0f / den;
    float o[DH];
#pragma unroll
    for (int d = 0; d < DH; d++) o[d] = 0.f;
#pragma unroll
    for (int j = 0; j < LMAXX; j++) {
        float a = sc[j] * inv;
        const __half2* vp = (const __half2*)(sV + j * DIM + h * DH);
#pragma unroll
        for (int d = 0; d < DH / 2; d++) {
            float2 vv = __half22float2(vp[d]);
            o[2 * d]     = fmaf(a, vv.x, o[2 * d]);
            o[2 * d + 1] = fmaf(a, vv.y, o[2 * d + 1]);
        }
    }
    __half* op = O + (size_t)(b * NTOK + qi) * DIM + h * DH;
#pragma unroll
    for (int d = 0; d < DH / 2; d++)
        ((__half2*)op)[d] = __floats2half2_rn(o[2 * d], o[2 * d + 1]);
}

// ---------------- dispatch helpers ------------------------------------------
__global__ void k_reset_cnt()
{
    int i = blockIdx.x * blockDim.x + threadIdx.x;
    if (i < NBUK) g_cnt[i] = 0;
}

__global__ void k_flatpos(const int* __restrict__ li)
{
    int i = blockIdx.x * blockDim.x + threadIdx.x;
    if (i >= NOBS) return;
    int d = li[3 * i], hh = li[3 * i + 1], w = li[3 * i + 2];
    int f = d * 1800 + hh * 60 + w;
    int pos = atomicAdd(&g_cnt[f], 1);
    g_row[i] = (pos < LMAXX) ? (f * LMAXX + pos) : -1;
}

__global__ void k_scatter(const __half* __restrict__ S)
{
    int wid  = (blockIdx.x * blockDim.x + threadIdx.x) >> 5;
    int lane = threadIdx.x & 31;
    if (wid >= NOBS) return;
    int dst = g_row[wid];
    if (dst < 0) return;
    ((uint4*)(g_ch + (size_t)dst * DIM))[lane] =
        ((const uint4*)(S + (size_t)wid * DIM))[lane];
}

__global__ void k_init_trx(const float* __restrict__ bg)
{
    int idx = blockIdx.x * blockDim.x + threadIdx.x;
    if (idx >= NOBS * DIM / 4) return;
    int row = idx >> 6;
    int t   = row & 7;
    int c4  = idx & 63;
    ((float4*)g_trx)[idx] = ((const float4*)bg)[t * 64 + c4];
}

// ---------------- fp32 -> half (input x) -------------------------------------
__global__ void k_tohalf(const float4* __restrict__ s, __half* __restrict__ d, int n4)
{
    int i = blockIdx.x * blockDim.x + threadIdx.x;
    if (i >= n4) return;
    float4 v = s[i];
    ((__half2*)d)[2 * i]     = __floats2half2_rn(v.x, v.y);
    ((__half2*)d)[2 * i + 1] = __floats2half2_rn(v.z, v.w);
}

// ---------------- weight transpose+convert: W[K,N] fp32 -> WT[N,K] half -----
__global__ void k_wt(const float* __restrict__ W, __half* __restrict__ T,
                     int K, int N)
{
    __shared__ float tile[32][33];
    size_t boff = (size_t)blockIdx.z * K * N;
    int n0 = blockIdx.x * 32, k0 = blockIdx.y * 32;
#pragma unroll
    for (int r = 0; r < 4; r++) {
        int k = k0 + threadIdx.y + r * 8;
        tile[threadIdx.y + r * 8][threadIdx.x] =
            W[boff + (size_t)k * N + n0 + threadIdx.x];
    }
    __syncthreads();
#pragma unroll
    for (int r = 0; r < 4; r++) {
        int n = n0 + threadIdx.y + r * 8;
        T[boff + (size_t)n * K + k0 + threadIdx.x] =
            __float2half(tile[threadIdx.x][threadIdx.y + r * 8]);
    }
}

// ---------------- launch ------------------------------------------------------
extern "C" void kernel_launch(void* const* d_in, const int* in_sizes, int n_in,
                              void* d_out, int out_size)
{
    const float* x     = (const float*)d_in[0];
    const int*   li    = (const int*)  d_in[1];
    const float* mlp_w = (const float*)d_in[2];
    const float* mlp_b = (const float*)d_in[3];
    const float* bg    = (const float*)d_in[4];
    const float* ln1g  = (const float*)d_in[5];
    const float* ln1b  = (const float*)d_in[6];
    const float* wq    = (const float*)d_in[7];
    const float* bq    = (const float*)d_in[8];
    const float* wk    = (const float*)d_in[9];
    const float* bk    = (const float*)d_in[10];
    const float* wv    = (const float*)d_in[11];
    const float* bv    = (const float*)d_in[12];
    const float* wo    = (const float*)d_in[13];
    const float* bo    = (const float*)d_in[14];
    const float* ln2g  = (const float*)d_in[15];
    const float* ln2b  = (const float*)d_in[16];
    const float* w1    = (const float*)d_in[17];
    const float* b1    = (const float*)d_in[18];
    const float* w2    = (const float*)d_in[19];
    const float* b2    = (const float*)d_in[20];
    const float* pw    = (const float*)d_in[21];
    const float* pb    = (const float*)d_in[22];
    float* out = (float*)d_out;
    (void)in_sizes; (void)n_in; (void)out_size;

    float *ptrx;
    __half *pA, *pB, *pC, *pK, *pV, *pW;
    int *pcnt;
    cudaGetSymbolAddress((void**)&ptrx, g_trx);
    cudaGetSymbolAddress((void**)&pA,   g_ah);
    cudaGetSymbolAddress((void**)&pB,   g_bh);
    cudaGetSymbolAddress((void**)&pC,   g_ch);
    cudaGetSymbolAddress((void**)&pK,   g_kh);
    cudaGetSymbolAddress((void**)&pV,   g_vh);
    cudaGetSymbolAddress((void**)&pW,   g_wh);
    cudaGetSymbolAddress((void**)&pcnt, g_cnt);

    cudaFuncSetAttribute(k_gemm_h, cudaFuncAttributeMaxDynamicSharedMemorySize,
                         GEMM_SMEM_H);

    // --- weight transpose+convert (deterministic, every call) ---
    dim3 wb(32, 8);
    k_wt<<<dim3(8, 8, 3),   wb>>>(mlp_w, pW + OFF_MLPW, 256, 256);
    k_wt<<<dim3(8, 8, 8),   wb>>>(wq,    pW + OFF_WQ,   256, 256);
    k_wt<<<dim3(8, 8, 8),   wb>>>(wk,    pW + OFF_WK,   256, 256);
    k_wt<<<dim3(8, 8, 8),   wb>>>(wv,    pW + OFF_WV,   256, 256);
    k_wt<<<dim3(8, 8, 8),   wb>>>(wo,    pW + OFF_WO,   256, 256);
    k_wt<<<dim3(32, 8, 8),  wb>>>(w1,    pW + OFF_W1,   256, 1024);
    k_wt<<<dim3(8, 32, 8),  wb>>>(w2,    pW + OFF_W2,   1024, 256);
    k_wt<<<dim3(16, 64, 1), wb>>>(pw,    pW + OFF_PROJ, 2048, 512);

    auto gemm = [&](const __half* A, int woff, const float* bias,
                    const float* res, const int* gate,
                    float* Cf, __half* Ch, int M, int N, int K, int act) {
        dim3 grid(N / 128, (M + 127) / 128);
        k_gemm_h<<<grid, 256, GEMM_SMEM_H>>>(A, pW + woff, bias, res, gate,
                                             Cf, Ch, M, N, K, act);
    };

    // --- obs feature MLP: fc1 -> gelu -> fc2 -> gelu -> fc3 ---
    k_tohalf<<<(NOBS * DIM / 4 + 255) / 256, 256>>>((const float4*)x, pB, NOBS * DIM / 4);
    gemm(pB, OFF_MLPW,             mlp_b,       nullptr, nullptr, nullptr, pA, NOBS, DIM, DIM, 1);
    gemm(pA, OFF_MLPW + 65536,     mlp_b + 256, nullptr, nullptr, nullptr, pB, NOBS, DIM, DIM, 1);
    gemm(pB, OFF_MLPW + 2 * 65536, mlp_b + 512, nullptr, nullptr, nullptr, pA, NOBS, DIM, DIM, 0);

    // --- dispatch into buckets ---
    k_reset_cnt<<<(NBUK + 255) / 256, 256>>>();
    k_flatpos<<<(NOBS + 255) / 256, 256>>>(li);
    k_scatter<<<NOBS / 8, 256>>>(pA);
    k_init_trx<<<NOBS * DIM / 4 / 256, 256>>>(bg);

    // --- batched K/V for all 8 layers (ctx is layer-invariant) ---
    // weight slab [N=8*256, K=256]; bk/bv are [DEPTH,DIM] = 2048 contiguous.
    gemm(pC, OFF_WK, bk, nullptr, nullptr, nullptr, pK, NOBS, DIM * DEPTH, DIM, 0);
    gemm(pC, OFF_WV, bv, nullptr, nullptr, nullptr, pV, NOBS, DIM * DEPTH, DIM, 0);

    // --- 8-layer cross-attention transformer ---
    for (int l = 0; l < DEPTH; l++) {
        k_ln<<<NBUK, 256>>>(ptrx, pB, ln1g + l * DIM, ln1b + l * DIM);
        gemm(pB, OFF_WQ + l * 65536, bq + l * DIM, nullptr, nullptr,
             nullptr, pA, NOBS, DIM, DIM, 0);
        k_attn<<<NBUK, 64>>>(pA, pK, pV, pB, l * DIM);
        gemm(pB, OFF_WO + l * 65536, bo + l * DIM, ptrx, nullptr,
             ptrx, nullptr, NOBS, DIM, DIM, 0);
        k_ln<<<NBUK, 256>>>(ptrx, pB, ln2g + l * DIM, ln2b + l * DIM);
        gemm(pB, OFF_W1 + l * DIM * FFND, b1 + l * FFND, nullptr, nullptr,
             nullptr, pA, NOBS, FFND, DIM, 1);
        if (l < DEPTH - 1) {
            gemm(pA, OFF_W2 + l * FFND * DIM, b2 + l * DIM, ptrx, nullptr,
                 ptrx, nullptr, NOBS, DIM, FFND, 0);
        } else {
            // last layer: emit half directly; [72000,256] half == [9000,2048] half
            gemm(pA, OFF_W2 + l * FFND * DIM, b2 + l * DIM, ptrx, nullptr,
                 nullptr, pB, NOBS, DIM, FFND, 0);
        }
    }

    // --- final projection, gated by occupancy ---
    gemm(pB, OFF_PROJ, pb, nullptr, pcnt, out, nullptr, NBUK, CLAT, OUTD, 0);
}